// round 9
// baseline (speedup 1.0000x reference)
#include <cuda_runtime.h>
#include <cuda_bf16.h>
#include <cstdint>
#include <math.h>

// Problem constants
#define PN   8
#define PF   16
#define PS   196
#define PD   1024
#define PH   8
#define PHD  128
#define PL   (1 + PF * PS)        // 3137
#define PNL  (PN * PL)            // 25096

// ---------------------------------------------------------------------------
// Scratch (device globals)
// ---------------------------------------------------------------------------
__device__ float g_t0[(size_t)PNL * PD];
__device__ float g_q [(size_t)PNL * PD];
__device__ float g_k [(size_t)PNL * PD];
__device__ float g_v [(size_t)PNL * PD];
__device__ __nv_bfloat16 g_ahi[(size_t)PNL * PD];
__device__ __nv_bfloat16 g_alo[(size_t)PNL * PD];
__device__ __nv_bfloat16 g_wth[5ull * 1024 * 1024];  // 5 transposed weights, hi
__device__ __nv_bfloat16 g_wtl[5ull * 1024 * 1024];  // lo

// ---------------------------------------------------------------------------
// Helpers
// ---------------------------------------------------------------------------
__device__ __forceinline__ uint32_t smem_u32(const void* p) {
    uint32_t a;
    asm("{ .reg .u64 t; cvta.to.shared.u64 t, %1; cvt.u32.u64 %0, t; }" : "=r"(a) : "l"(p));
    return a;
}

#define LDM_X4(d0, d1, d2, d3, addr)                                             \
    asm volatile("ldmatrix.sync.aligned.m8n8.x4.shared.b16 {%0,%1,%2,%3}, [%4];" \
                 : "=r"(d0), "=r"(d1), "=r"(d2), "=r"(d3) : "r"(addr))
#define MMA_BF16(d, a, b0, b1)                                                   \
    asm volatile("mma.sync.aligned.m16n8k16.row.col.f32.bf16.bf16.f32 "          \
                 "{%0,%1,%2,%3}, {%4,%5,%6,%7}, {%8,%9}, {%0,%1,%2,%3};"         \
                 : "+f"((d)[0]), "+f"((d)[1]), "+f"((d)[2]), "+f"((d)[3])        \
                 : "r"((a)[0]), "r"((a)[1]), "r"((a)[2]), "r"((a)[3]),           \
                   "r"(b0), "r"(b1))
#define CP_ASYNC16(dst, src, sz)                                                 \
    asm volatile("cp.async.cg.shared.global [%0], [%1], 16, %2;"                 \
                 :: "r"(dst), "l"(src), "r"(sz) : "memory")
#define CP_COMMIT()  asm volatile("cp.async.commit_group;" ::: "memory")
#define CP_WAIT_ALL() asm volatile("cp.async.wait_all;" ::: "memory")

// ---------------------------------------------------------------------------
// Split fp32 -> bf16 hi + lo (elementwise, float4)
// ---------------------------------------------------------------------------
__global__ __launch_bounds__(256)
void split_kernel(const float* __restrict__ in, __nv_bfloat16* __restrict__ hi,
                  __nv_bfloat16* __restrict__ lo, int n4)
{
    int i = blockIdx.x * blockDim.x + threadIdx.x;
    if (i >= n4) return;
    float4 x = ((const float4*)in)[i];
    __nv_bfloat16 h0 = __float2bfloat16_rn(x.x);
    __nv_bfloat16 h1 = __float2bfloat16_rn(x.y);
    __nv_bfloat16 h2 = __float2bfloat16_rn(x.z);
    __nv_bfloat16 h3 = __float2bfloat16_rn(x.w);
    __nv_bfloat16 l0 = __float2bfloat16_rn(x.x - __bfloat162float(h0));
    __nv_bfloat16 l1 = __float2bfloat16_rn(x.y - __bfloat162float(h1));
    __nv_bfloat16 l2 = __float2bfloat16_rn(x.z - __bfloat162float(h2));
    __nv_bfloat16 l3 = __float2bfloat16_rn(x.w - __bfloat162float(h3));
    ((__nv_bfloat162*)hi)[2 * i]     = __nv_bfloat162(h0, h1);
    ((__nv_bfloat162*)hi)[2 * i + 1] = __nv_bfloat162(h2, h3);
    ((__nv_bfloat162*)lo)[2 * i]     = __nv_bfloat162(l0, l1);
    ((__nv_bfloat162*)lo)[2 * i + 1] = __nv_bfloat162(l2, l3);
}

// ---------------------------------------------------------------------------
// Transpose + split weight: W[k][n] fp32 -> Wt_hi[n][k], Wt_lo[n][k] bf16
// ---------------------------------------------------------------------------
__global__ __launch_bounds__(256)
void wsplit_kernel(const float* __restrict__ W, __nv_bfloat16* __restrict__ hi,
                   __nv_bfloat16* __restrict__ lo)
{
    __shared__ float t[32][33];
    const int bx = blockIdx.x, by = blockIdx.y;
    const int tx = threadIdx.x, ty = threadIdx.y;   // 32 x 8
    #pragma unroll
    for (int i = 0; i < 32; i += 8)
        t[ty + i][tx] = W[(size_t)(by * 32 + ty + i) * 1024 + bx * 32 + tx];
    __syncthreads();
    #pragma unroll
    for (int i = 0; i < 32; i += 8) {
        float v = t[tx][ty + i];
        __nv_bfloat16 h = __float2bfloat16_rn(v);
        __nv_bfloat16 l = __float2bfloat16_rn(v - __bfloat162float(h));
        size_t o = (size_t)(bx * 32 + ty + i) * 1024 + by * 32 + tx;
        hi[o] = h;
        lo[o] = l;
    }
}

// ---------------------------------------------------------------------------
// Warp-MMA bf16-split GEMM, cp.async 2-stage double buffer, 1 sync per chunk.
// C[M,1024] = A[M,1024] * Bt[1024,1024]^T (+bias)
// Tile 128x128, BK=32; 8 warps 2(M)x4(N), each 64x32 via 4x4 m16n8k16.
// Per chunk 3 passes: Ah*Bh, Ah*Bl, Al*Bh (fp32 accum).
//
// Sync argument: per-warp reads (LDSM) of stage c-1 precede the top-of-iter-c
// __syncthreads in program order; the refill of buffer (c+1)&1 = (c-1)&1 is
// issued after that same barrier -> no trailing barrier needed.
// ---------------------------------------------------------------------------
#define ST 40                        // smem row stride in bf16 (80B)
#define ARR_B   (128 * ST * 2)       // bytes per array (10240)
#define STAGE_B (4 * ARR_B)          // bytes per stage (40960)
#define GSMEM   (2 * STAGE_B)        // total dynamic smem (81920)

extern __shared__ __nv_bfloat16 dynsmem[];

__global__ __launch_bounds__(256, 2)
void gemm_mma(int M, const __nv_bfloat16* __restrict__ aHi, const __nv_bfloat16* __restrict__ aLo,
              const __nv_bfloat16* __restrict__ btHi, const __nv_bfloat16* __restrict__ btLo,
              const float* __restrict__ bias, float* __restrict__ C)
{
    const int tid  = threadIdx.x;
    const int wid  = tid >> 5, lane = tid & 31;
    const int m0   = blockIdx.y * 128, n0 = blockIdx.x * 128;
    const int wm   = (wid >> 2) * 64;     // warp M origin
    const int wn   = (wid & 3) * 32;      // warp N origin

    const uint32_t sbase = smem_u32(dynsmem);

    float acc[4][4][4];
    #pragma unroll
    for (int mt = 0; mt < 4; mt++)
        #pragma unroll
        for (int nt = 0; nt < 4; nt++)
            #pragma unroll
            for (int e = 0; e < 4; e++) acc[mt][nt][e] = 0.0f;

    // cp.async fill: 2048 16B chunks per stage; idx = tid + i*256, i in 0..7
    // group = idx>>9 (0:Ah 1:Al 2:Bh 3:Bl), within = idx&511, row = within>>2, c16 = within&3
    #define LOAD_STAGE(c, sb) do {                                               \
        const int kk0 = (c) * 32;                                                \
        _Pragma("unroll")                                                        \
        for (int i = 0; i < 8; i++) {                                            \
            int idx = tid + i * 256;                                             \
            int grp = idx >> 9, within = idx & 511;                              \
            int row = within >> 2, c16 = within & 3;                             \
            int kc  = kk0 + c16 * 8;                                             \
            uint32_t dst = (sb) + grp * ARR_B + (row * ST + c16 * 8) * 2;        \
            const __nv_bfloat16* src;                                            \
            uint32_t sz = 16;                                                    \
            if (grp < 2) {                                                       \
                int m = m0 + row;                                                \
                if (m >= M) { m = m0; sz = 0; }                                  \
                src = (grp == 0 ? aHi : aLo) + (size_t)m * 1024 + kc;            \
            } else {                                                             \
                src = (grp == 2 ? btHi : btLo) + (size_t)(n0 + row) * 1024 + kc; \
            }                                                                    \
            CP_ASYNC16(dst, src, sz);                                            \
        }                                                                        \
        CP_COMMIT();                                                             \
    } while (0)

    LOAD_STAGE(0, sbase);

    // ldmatrix lane addressing
    const int aRow = wm + (lane & 15);
    const int aKof = (lane >> 4) * 8;
    const int bRow = wn + (lane & 7) + ((lane >> 4) << 3);   // x4 B: 2 n-tiles
    const int bKof = ((lane >> 3) & 1) * 8;

    for (int c = 0; c < 32; c++) {
        const uint32_t cur = sbase + (c & 1) * STAGE_B;
        CP_WAIT_ALL();
        __syncthreads();                 // stage c visible to all; readers of (c+1)&1 done
        if (c < 31) LOAD_STAGE(c + 1, sbase + ((c + 1) & 1) * STAGE_B);

        const uint32_t Ah = cur, Al = cur + ARR_B;
        const uint32_t Bh = cur + 2 * ARR_B, Bl = cur + 3 * ARR_B;

        #pragma unroll
        for (int ks = 0; ks < 2; ks++) {
            const int kb = ks * 16;
            uint32_t ah[4][4], al[4][4], bh[2][4], bl[2][4];
            #pragma unroll
            for (int mt = 0; mt < 4; mt++) {
                uint32_t off = ((aRow + mt * 16) * ST + kb + aKof) * 2;
                LDM_X4(ah[mt][0], ah[mt][1], ah[mt][2], ah[mt][3], Ah + off);
                LDM_X4(al[mt][0], al[mt][1], al[mt][2], al[mt][3], Al + off);
            }
            #pragma unroll
            for (int p = 0; p < 2; p++) {
                uint32_t off = ((bRow + p * 16) * ST + kb + bKof) * 2;
                LDM_X4(bh[p][0], bh[p][1], bh[p][2], bh[p][3], Bh + off);
                LDM_X4(bl[p][0], bl[p][1], bl[p][2], bl[p][3], Bl + off);
            }
            #pragma unroll
            for (int mt = 0; mt < 4; mt++)
                #pragma unroll
                for (int nt = 0; nt < 4; nt++) {
                    const int p = nt >> 1, o = (nt & 1) * 2;
                    MMA_BF16(acc[mt][nt], ah[mt], bh[p][o], bh[p][o + 1]);
                    MMA_BF16(acc[mt][nt], ah[mt], bl[p][o], bl[p][o + 1]);
                    MMA_BF16(acc[mt][nt], al[mt], bh[p][o], bh[p][o + 1]);
                }
        }
    }
    #undef LOAD_STAGE

    // epilogue
    const int r     = lane >> 2;
    const int cpair = (lane & 3) * 2;
    #pragma unroll
    for (int nt = 0; nt < 4; nt++) {
        const int n  = n0 + wn + nt * 8 + cpair;
        float b0 = 0.f, b1 = 0.f;
        if (bias) { b0 = bias[n]; b1 = bias[n + 1]; }
        #pragma unroll
        for (int mt = 0; mt < 4; mt++) {
            const int m = m0 + wm + mt * 16 + r;
            if (m < M) {
                float2 v0 = make_float2(acc[mt][nt][0] + b0, acc[mt][nt][1] + b1);
                *(float2*)(C + (size_t)m * 1024 + n) = v0;
            }
            if (m + 8 < M) {
                float2 v1 = make_float2(acc[mt][nt][2] + b0, acc[mt][nt][3] + b1);
                *(float2*)(C + (size_t)(m + 8) * 1024 + n) = v1;
            }
        }
    }
}

// ---------------------------------------------------------------------------
// LayerNorm over rows of 1024, output split directly to bf16 hi/lo
// ---------------------------------------------------------------------------
__global__ __launch_bounds__(256)
void ln_split_kernel(const float* __restrict__ in, const float* __restrict__ gamma,
                     const float* __restrict__ beta, __nv_bfloat16* __restrict__ hi,
                     __nv_bfloat16* __restrict__ lo)
{
    const int row = blockIdx.x;
    const int t   = threadIdx.x;
    const float4* x4 = (const float4*)(in + (size_t)row * PD);
    float4 xv = x4[t];

    float s  = xv.x + xv.y + xv.z + xv.w;
    float s2 = xv.x * xv.x + xv.y * xv.y + xv.z * xv.z + xv.w * xv.w;

    __shared__ float red[2][8];
    #pragma unroll
    for (int o = 16; o > 0; o >>= 1) {
        s  += __shfl_down_sync(0xFFFFFFFFu, s,  o);
        s2 += __shfl_down_sync(0xFFFFFFFFu, s2, o);
    }
    const int wid = t >> 5, lid = t & 31;
    if (lid == 0) { red[0][wid] = s; red[1][wid] = s2; }
    __syncthreads();
    if (wid == 0) {
        float a = (lid < 8) ? red[0][lid] : 0.f;
        float b = (lid < 8) ? red[1][lid] : 0.f;
        #pragma unroll
        for (int o = 4; o > 0; o >>= 1) {
            a += __shfl_down_sync(0xFFFFFFFFu, a, o);
            b += __shfl_down_sync(0xFFFFFFFFu, b, o);
        }
        if (lid == 0) { red[0][0] = a; red[1][0] = b; }
    }
    __syncthreads();

    const float mean = red[0][0] * (1.0f / PD);
    const float var  = red[1][0] * (1.0f / PD) - mean * mean;
    const float rstd = rsqrtf(var + 1e-5f);

    float4 gv = ((const float4*)gamma)[t];
    float4 bv = ((const float4*)beta)[t];
    float o0 = (xv.x - mean) * rstd * gv.x + bv.x;
    float o1 = (xv.y - mean) * rstd * gv.y + bv.y;
    float o2 = (xv.z - mean) * rstd * gv.z + bv.z;
    float o3 = (xv.w - mean) * rstd * gv.w + bv.w;

    __nv_bfloat16 h0 = __float2bfloat16_rn(o0);
    __nv_bfloat16 h1 = __float2bfloat16_rn(o1);
    __nv_bfloat16 h2 = __float2bfloat16_rn(o2);
    __nv_bfloat16 h3 = __float2bfloat16_rn(o3);
    __nv_bfloat16 l0 = __float2bfloat16_rn(o0 - __bfloat162float(h0));
    __nv_bfloat16 l1 = __float2bfloat16_rn(o1 - __bfloat162float(h1));
    __nv_bfloat16 l2 = __float2bfloat16_rn(o2 - __bfloat162float(h2));
    __nv_bfloat16 l3 = __float2bfloat16_rn(o3 - __bfloat162float(h3));

    const size_t o = (size_t)row * PD / 2 + 2 * t;
    ((__nv_bfloat162*)hi)[o]     = __nv_bfloat162(h0, h1);
    ((__nv_bfloat162*)hi)[o + 1] = __nv_bfloat162(h2, h3);
    ((__nv_bfloat162*)lo)[o]     = __nv_bfloat162(l0, l1);
    ((__nv_bfloat162*)lo)[o + 1] = __nv_bfloat162(l2, l3);
}

// ---------------------------------------------------------------------------
// Temporal attention (att_type == 1). Reference tile quirk: feature K/V for
// attention batch b = nh*S + s comes from head-batch (b % 64).
// ---------------------------------------------------------------------------
__global__ __launch_bounds__(128)
void attn_kernel(const float* __restrict__ Q, const float* __restrict__ Kt,
                 const float* __restrict__ Vt, float* __restrict__ O)
{
    constexpr int PITCH = 129;
    __shared__ float qs[16 * PITCH];
    __shared__ float ks[17 * PITCH];
    __shared__ float vs[17 * PITCH];
    __shared__ float ps[16 * 18];

    const int s  = blockIdx.x;         // 0..195
    const int nh = blockIdx.y;         // 0..63
    const int n  = nh >> 3;
    const int h  = nh & 7;
    const int t  = threadIdx.x;        // 0..127

    const int fb = (nh * PS + s) & 63;
    const int fn = fb >> 3;
    const int fh = fb & 7;
    const size_t featKV = ((size_t)fn * PL) * PD + (size_t)fh * PHD;
    ks[t] = Kt[featKV + t];
    vs[t] = Vt[featKV + t];

    for (int f = 0; f < PF; f++) {
        const size_t r = ((size_t)n * PL + 1 + (size_t)f * PS + s) * PD + (size_t)h * PHD;
        qs[f * PITCH + t]       = Q [r + t];
        ks[(f + 1) * PITCH + t] = Kt[r + t];
        vs[(f + 1) * PITCH + t] = Vt[r + t];
    }
    __syncthreads();

    const float scale = 0.088388347648318447f;   // 1/sqrt(128)
    for (int p = t; p < 16 * 17; p += 128) {
        const int i = p / 17, j = p % 17;
        float acc = 0.f;
        #pragma unroll 8
        for (int d = 0; d < PHD; d++)
            acc = fmaf(qs[i * PITCH + d], ks[j * PITCH + d], acc);
        ps[i * 18 + j] = acc * scale;
    }
    __syncthreads();

    if (t < 16) {
        float mx = -1e30f;
        #pragma unroll
        for (int j = 0; j < 17; j++) mx = fmaxf(mx, ps[t * 18 + j]);
        float sum = 0.f;
        #pragma unroll
        for (int j = 0; j < 17; j++) {
            const float e = __expf(ps[t * 18 + j] - mx);
            ps[t * 18 + j] = e;
            sum += e;
        }
        const float inv = 1.0f / sum;
        #pragma unroll
        for (int j = 0; j < 17; j++) ps[t * 18 + j] *= inv;
    }
    __syncthreads();

    for (int i = 0; i < PF; i++) {
        float acc = 0.f;
        #pragma unroll
        for (int j = 0; j < 17; j++)
            acc = fmaf(ps[i * 18 + j], vs[j * PITCH + t], acc);
        O[((size_t)n * PL + 1 + (size_t)i * PS + s) * PD + (size_t)h * PHD + t] = acc;
    }

    if (s == 0) {
        const size_t featRow = ((size_t)n * PL) * PD + (size_t)h * PHD;
        O[featRow + t] = Q[featRow + t];
    }
}

// ---------------------------------------------------------------------------
// Launch (ordered so gemm_mma is ncu launch index 5)
// ---------------------------------------------------------------------------
extern "C" void kernel_launch(void* const* d_in, const int* in_sizes, int n_in,
                              void* d_out, int out_size)
{
    (void)in_sizes; (void)n_in; (void)out_size;

    const float* x        = (const float*)d_in[0];
    const float* W_in     = (const float*)d_in[1];
    const float* b_in     = (const float*)d_in[2];
    const float* g_in     = (const float*)d_in[3];
    const float* beta_in  = (const float*)d_in[4];
    const float* W_q      = (const float*)d_in[5];
    const float* W_k      = (const float*)d_in[6];
    const float* W_v      = (const float*)d_in[7];
    const float* g_out    = (const float*)d_in[8];
    const float* beta_out = (const float*)d_in[9];
    const float* W_out    = (const float*)d_in[10];
    const float* b_out    = (const float*)d_in[11];
    float* out = (float*)d_out;

    float *t0, *q, *k, *v;
    __nv_bfloat16 *ahi, *alo, *wth, *wtl;
    cudaGetSymbolAddress((void**)&t0,  g_t0);
    cudaGetSymbolAddress((void**)&q,   g_q);
    cudaGetSymbolAddress((void**)&k,   g_k);
    cudaGetSymbolAddress((void**)&v,   g_v);
    cudaGetSymbolAddress((void**)&ahi, g_ahi);
    cudaGetSymbolAddress((void**)&alo, g_alo);
    cudaGetSymbolAddress((void**)&wth, g_wth);
    cudaGetSymbolAddress((void**)&wtl, g_wtl);

    cudaFuncSetAttribute(gemm_mma, cudaFuncAttributeMaxDynamicSharedMemorySize, GSMEM);

    const size_t WSLOT = 1024ull * 1024ull;
    const dim3 wsGrid(32, 32), wsBlk(32, 8);
    const int n4 = PNL * PD / 4;
    const int splitBlocks = (n4 + 255) / 256;
    const dim3 gemmGrid(8, 197);      // (N-tiles, M-tiles)
    const dim3 gemmBlk(256);

    // launch idx:                                            0
    wsplit_kernel<<<wsGrid, wsBlk>>>(W_in,  wth + 0 * WSLOT, wtl + 0 * WSLOT);
    // 1. t0 = x @ W_in + b_in                                1, 2
    split_kernel<<<splitBlocks, 256>>>(x, ahi, alo, n4);
    gemm_mma<<<gemmGrid, gemmBlk, GSMEM>>>(PNL, ahi, alo, wth + 0 * WSLOT, wtl + 0 * WSLOT, b_in, t0);
    // 2. (ahi, alo) = split(LN(t0))                          3
    ln_split_kernel<<<PNL, 256>>>(t0, g_in, beta_in, ahi, alo);
    // 3. q/k/v projections                                   4, 5 (gemm_q = idx 5), 6, 7, 8, 9
    wsplit_kernel<<<wsGrid, wsBlk>>>(W_q, wth + 1 * WSLOT, wtl + 1 * WSLOT);
    gemm_mma<<<gemmGrid, gemmBlk, GSMEM>>>(PNL, ahi, alo, wth + 1 * WSLOT, wtl + 1 * WSLOT, nullptr, q);
    wsplit_kernel<<<wsGrid, wsBlk>>>(W_k, wth + 2 * WSLOT, wtl + 2 * WSLOT);
    gemm_mma<<<gemmGrid, gemmBlk, GSMEM>>>(PNL, ahi, alo, wth + 2 * WSLOT, wtl + 2 * WSLOT, nullptr, k);
    wsplit_kernel<<<wsGrid, wsBlk>>>(W_v, wth + 3 * WSLOT, wtl + 3 * WSLOT);
    gemm_mma<<<gemmGrid, gemmBlk, GSMEM>>>(PNL, ahi, alo, wth + 3 * WSLOT, wtl + 3 * WSLOT, nullptr, v);
    // 4. temporal attention -> t0
    attn_kernel<<<dim3(PS, PN * PH), 128>>>(q, k, v, t0);
    // 5. (ahi, alo) = split(LN(t0))
    ln_split_kernel<<<PNL, 256>>>(t0, g_out, beta_out, ahi, alo);
    // 6. out = x1 @ W_out + b_out
    wsplit_kernel<<<wsGrid, wsBlk>>>(W_out, wth + 4 * WSLOT, wtl + 4 * WSLOT);
    gemm_mma<<<gemmGrid, gemmBlk, GSMEM>>>(PNL, ahi, alo, wth + 4 * WSLOT, wtl + 4 * WSLOT, b_out, out);
}

// round 10
// speedup vs baseline: 1.0125x; 1.0125x over previous
#include <cuda_runtime.h>
#include <cuda_bf16.h>
#include <cstdint>
#include <math.h>

// Problem constants
#define PN   8
#define PF   16
#define PS   196
#define PD   1024
#define PH   8
#define PHD  128
#define PL   (1 + PF * PS)        // 3137
#define PNL  (PN * PL)            // 25096

// ---------------------------------------------------------------------------
// Scratch (device globals)
// ---------------------------------------------------------------------------
__device__ float g_t0[(size_t)PNL * PD];
__device__ float g_q [(size_t)PNL * PD];
__device__ float g_k [(size_t)PNL * PD];
__device__ float g_v [(size_t)PNL * PD];
__device__ __nv_bfloat16 g_ahi[(size_t)PNL * PD];
__device__ __nv_bfloat16 g_alo[(size_t)PNL * PD];
__device__ __nv_bfloat16 g_wth[5ull * 1024 * 1024];  // 5 transposed weights, hi
__device__ __nv_bfloat16 g_wtl[5ull * 1024 * 1024];  // lo

// ---------------------------------------------------------------------------
// Helpers
// ---------------------------------------------------------------------------
__device__ __forceinline__ uint32_t smem_u32(const void* p) {
    uint32_t a;
    asm("{ .reg .u64 t; cvta.to.shared.u64 t, %1; cvt.u32.u64 %0, t; }" : "=r"(a) : "l"(p));
    return a;
}

#define LDM_X4(d0, d1, d2, d3, addr)                                             \
    asm volatile("ldmatrix.sync.aligned.m8n8.x4.shared.b16 {%0,%1,%2,%3}, [%4];" \
                 : "=r"(d0), "=r"(d1), "=r"(d2), "=r"(d3) : "r"(addr))
#define MMA_BF16(d, a0, a1, a2, a3, b0, b1)                                      \
    asm volatile("mma.sync.aligned.m16n8k16.row.col.f32.bf16.bf16.f32 "          \
                 "{%0,%1,%2,%3}, {%4,%5,%6,%7}, {%8,%9}, {%0,%1,%2,%3};"         \
                 : "+f"((d)[0]), "+f"((d)[1]), "+f"((d)[2]), "+f"((d)[3])        \
                 : "r"(a0), "r"(a1), "r"(a2), "r"(a3), "r"(b0), "r"(b1))
#define CP_ASYNC16(dst, src, sz)                                                 \
    asm volatile("cp.async.cg.shared.global [%0], [%1], 16, %2;"                 \
                 :: "r"(dst), "l"(src), "r"(sz) : "memory")
#define CP_COMMIT()  asm volatile("cp.async.commit_group;" ::: "memory")
#define CP_WAIT_ALL() asm volatile("cp.async.wait_all;" ::: "memory")

// ---------------------------------------------------------------------------
// Split fp32 -> bf16 hi + lo (elementwise, float4)
// ---------------------------------------------------------------------------
__global__ __launch_bounds__(256)
void split_kernel(const float* __restrict__ in, __nv_bfloat16* __restrict__ hi,
                  __nv_bfloat16* __restrict__ lo, int n4)
{
    int i = blockIdx.x * blockDim.x + threadIdx.x;
    if (i >= n4) return;
    float4 x = ((const float4*)in)[i];
    __nv_bfloat16 h0 = __float2bfloat16_rn(x.x);
    __nv_bfloat16 h1 = __float2bfloat16_rn(x.y);
    __nv_bfloat16 h2 = __float2bfloat16_rn(x.z);
    __nv_bfloat16 h3 = __float2bfloat16_rn(x.w);
    __nv_bfloat16 l0 = __float2bfloat16_rn(x.x - __bfloat162float(h0));
    __nv_bfloat16 l1 = __float2bfloat16_rn(x.y - __bfloat162float(h1));
    __nv_bfloat16 l2 = __float2bfloat16_rn(x.z - __bfloat162float(h2));
    __nv_bfloat16 l3 = __float2bfloat16_rn(x.w - __bfloat162float(h3));
    ((__nv_bfloat162*)hi)[2 * i]     = __nv_bfloat162(h0, h1);
    ((__nv_bfloat162*)hi)[2 * i + 1] = __nv_bfloat162(h2, h3);
    ((__nv_bfloat162*)lo)[2 * i]     = __nv_bfloat162(l0, l1);
    ((__nv_bfloat162*)lo)[2 * i + 1] = __nv_bfloat162(l2, l3);
}

// ---------------------------------------------------------------------------
// Transpose + split weight: W[k][n] fp32 -> Wt_hi[n][k], Wt_lo[n][k] bf16
// ---------------------------------------------------------------------------
__global__ __launch_bounds__(256)
void wsplit_kernel(const float* __restrict__ W, __nv_bfloat16* __restrict__ hi,
                   __nv_bfloat16* __restrict__ lo)
{
    __shared__ float t[32][33];
    const int bx = blockIdx.x, by = blockIdx.y;
    const int tx = threadIdx.x, ty = threadIdx.y;   // 32 x 8
    #pragma unroll
    for (int i = 0; i < 32; i += 8)
        t[ty + i][tx] = W[(size_t)(by * 32 + ty + i) * 1024 + bx * 32 + tx];
    __syncthreads();
    #pragma unroll
    for (int i = 0; i < 32; i += 8) {
        float v = t[tx][ty + i];
        __nv_bfloat16 h = __float2bfloat16_rn(v);
        __nv_bfloat16 l = __float2bfloat16_rn(v - __bfloat162float(h));
        size_t o = (size_t)(bx * 32 + ty + i) * 1024 + by * 32 + tx;
        hi[o] = h;
        lo[o] = l;
    }
}

// ---------------------------------------------------------------------------
// Warp-MMA bf16-split GEMM, cp.async 2-stage double buffer, 1 sync per chunk.
// C[M,1024] = A[M,1024] * Bt[1024,1024]^T (+bias)
// Tile 128x128, BK=32; 8 warps 2(M)x4(N), each 64x32 via 4x4 m16n8k16.
// Per chunk 3 passes: Ah*Bh, Ah*Bl, Al*Bh (fp32 accum).
//
// Register-liveness note: B fragments (16 regs) are loaded once per ks-step;
// A fragments (8 regs) are loaded per-mt and consumed immediately, keeping the
// live set ~= 64 acc + 16 B + 8 A + overhead < 128 (no spills at 2 CTAs/SM).
// ---------------------------------------------------------------------------
#define ST 40                        // smem row stride in bf16 (80B)
#define ARR_B   (128 * ST * 2)       // bytes per array (10240)
#define STAGE_B (4 * ARR_B)          // bytes per stage (40960)
#define GSMEM   (2 * STAGE_B)        // total dynamic smem (81920)

extern __shared__ __nv_bfloat16 dynsmem[];

__global__ __launch_bounds__(256, 2)
void gemm_mma(int M, const __nv_bfloat16* __restrict__ aHi, const __nv_bfloat16* __restrict__ aLo,
              const __nv_bfloat16* __restrict__ btHi, const __nv_bfloat16* __restrict__ btLo,
              const float* __restrict__ bias, float* __restrict__ C)
{
    const int tid  = threadIdx.x;
    const int wid  = tid >> 5, lane = tid & 31;
    const int m0   = blockIdx.y * 128, n0 = blockIdx.x * 128;
    const int wm   = (wid >> 2) * 64;     // warp M origin
    const int wn   = (wid & 3) * 32;      // warp N origin

    const uint32_t sbase = smem_u32(dynsmem);

    float acc[4][4][4];
    #pragma unroll
    for (int mt = 0; mt < 4; mt++)
        #pragma unroll
        for (int nt = 0; nt < 4; nt++)
            #pragma unroll
            for (int e = 0; e < 4; e++) acc[mt][nt][e] = 0.0f;

    // cp.async fill: 2048 16B chunks per stage; idx = tid + i*256, i in 0..7
    // group = idx>>9 (0:Ah 1:Al 2:Bh 3:Bl), within = idx&511, row = within>>2, c16 = within&3
    #define LOAD_STAGE(c, sb) do {                                               \
        const int kk0 = (c) * 32;                                                \
        _Pragma("unroll")                                                        \
        for (int i = 0; i < 8; i++) {                                            \
            int idx = tid + i * 256;                                             \
            int grp = idx >> 9, within = idx & 511;                              \
            int row = within >> 2, c16 = within & 3;                             \
            int kc  = kk0 + c16 * 8;                                             \
            uint32_t dst = (sb) + grp * ARR_B + (row * ST + c16 * 8) * 2;        \
            const __nv_bfloat16* src;                                            \
            uint32_t sz = 16;                                                    \
            if (grp < 2) {                                                       \
                int m = m0 + row;                                                \
                if (m >= M) { m = m0; sz = 0; }                                  \
                src = (grp == 0 ? aHi : aLo) + (size_t)m * 1024 + kc;            \
            } else {                                                             \
                src = (grp == 2 ? btHi : btLo) + (size_t)(n0 + row) * 1024 + kc; \
            }                                                                    \
            CP_ASYNC16(dst, src, sz);                                            \
        }                                                                        \
        CP_COMMIT();                                                             \
    } while (0)

    LOAD_STAGE(0, sbase);

    // ldmatrix lane addressing
    const int aRow = wm + (lane & 15);
    const int aKof = (lane >> 4) * 8;
    const int bRow = wn + (lane & 7) + ((lane >> 4) << 3);   // x4 B: 2 n-tiles
    const int bKof = ((lane >> 3) & 1) * 8;

    for (int c = 0; c < 32; c++) {
        const uint32_t cur = sbase + (c & 1) * STAGE_B;
        CP_WAIT_ALL();
        __syncthreads();                 // stage c visible; readers of (c+1)&1 done
        if (c < 31) LOAD_STAGE(c + 1, sbase + ((c + 1) & 1) * STAGE_B);

        const uint32_t Ah = cur, Al = cur + ARR_B;
        const uint32_t Bh = cur + 2 * ARR_B, Bl = cur + 3 * ARR_B;

        #pragma unroll
        for (int ks = 0; ks < 2; ks++) {
            const int kb = ks * 16;
            // B fragments for the whole warp-tile first (16 regs live)
            uint32_t bh[2][4], bl[2][4];
            #pragma unroll
            for (int p = 0; p < 2; p++) {
                uint32_t off = ((bRow + p * 16) * ST + kb + bKof) * 2;
                LDM_X4(bh[p][0], bh[p][1], bh[p][2], bh[p][3], Bh + off);
                LDM_X4(bl[p][0], bl[p][1], bl[p][2], bl[p][3], Bl + off);
            }
            // A fragments per mt, consumed immediately (8 regs live)
            #pragma unroll
            for (int mt = 0; mt < 4; mt++) {
                uint32_t a0, a1, a2, a3, x0, x1, x2, x3;
                uint32_t off = ((aRow + mt * 16) * ST + kb + aKof) * 2;
                LDM_X4(a0, a1, a2, a3, Ah + off);
                LDM_X4(x0, x1, x2, x3, Al + off);
                #pragma unroll
                for (int nt = 0; nt < 4; nt++) {
                    const int p = nt >> 1, o = (nt & 1) * 2;
                    MMA_BF16(acc[mt][nt], a0, a1, a2, a3, bh[p][o], bh[p][o + 1]);
                    MMA_BF16(acc[mt][nt], a0, a1, a2, a3, bl[p][o], bl[p][o + 1]);
                    MMA_BF16(acc[mt][nt], x0, x1, x2, x3, bh[p][o], bh[p][o + 1]);
                }
            }
        }
    }
    #undef LOAD_STAGE

    // epilogue
    const int r     = lane >> 2;
    const int cpair = (lane & 3) * 2;
    #pragma unroll
    for (int nt = 0; nt < 4; nt++) {
        const int n  = n0 + wn + nt * 8 + cpair;
        float b0 = 0.f, b1 = 0.f;
        if (bias) { b0 = bias[n]; b1 = bias[n + 1]; }
        #pragma unroll
        for (int mt = 0; mt < 4; mt++) {
            const int m = m0 + wm + mt * 16 + r;
            if (m < M) {
                float2 v0 = make_float2(acc[mt][nt][0] + b0, acc[mt][nt][1] + b1);
                *(float2*)(C + (size_t)m * 1024 + n) = v0;
            }
            if (m + 8 < M) {
                float2 v1 = make_float2(acc[mt][nt][2] + b0, acc[mt][nt][3] + b1);
                *(float2*)(C + (size_t)(m + 8) * 1024 + n) = v1;
            }
        }
    }
}

// ---------------------------------------------------------------------------
// LayerNorm over rows of 1024, output split directly to bf16 hi/lo
// ---------------------------------------------------------------------------
__global__ __launch_bounds__(256)
void ln_split_kernel(const float* __restrict__ in, const float* __restrict__ gamma,
                     const float* __restrict__ beta, __nv_bfloat16* __restrict__ hi,
                     __nv_bfloat16* __restrict__ lo)
{
    const int row = blockIdx.x;
    const int t   = threadIdx.x;
    const float4* x4 = (const float4*)(in + (size_t)row * PD);
    float4 xv = x4[t];

    float s  = xv.x + xv.y + xv.z + xv.w;
    float s2 = xv.x * xv.x + xv.y * xv.y + xv.z * xv.z + xv.w * xv.w;

    __shared__ float red[2][8];
    #pragma unroll
    for (int o = 16; o > 0; o >>= 1) {
        s  += __shfl_down_sync(0xFFFFFFFFu, s,  o);
        s2 += __shfl_down_sync(0xFFFFFFFFu, s2, o);
    }
    const int wid = t >> 5, lid = t & 31;
    if (lid == 0) { red[0][wid] = s; red[1][wid] = s2; }
    __syncthreads();
    if (wid == 0) {
        float a = (lid < 8) ? red[0][lid] : 0.f;
        float b = (lid < 8) ? red[1][lid] : 0.f;
        #pragma unroll
        for (int o = 4; o > 0; o >>= 1) {
            a += __shfl_down_sync(0xFFFFFFFFu, a, o);
            b += __shfl_down_sync(0xFFFFFFFFu, b, o);
        }
        if (lid == 0) { red[0][0] = a; red[1][0] = b; }
    }
    __syncthreads();

    const float mean = red[0][0] * (1.0f / PD);
    const float var  = red[1][0] * (1.0f / PD) - mean * mean;
    const float rstd = rsqrtf(var + 1e-5f);

    float4 gv = ((const float4*)gamma)[t];
    float4 bv = ((const float4*)beta)[t];
    float o0 = (xv.x - mean) * rstd * gv.x + bv.x;
    float o1 = (xv.y - mean) * rstd * gv.y + bv.y;
    float o2 = (xv.z - mean) * rstd * gv.z + bv.z;
    float o3 = (xv.w - mean) * rstd * gv.w + bv.w;

    __nv_bfloat16 h0 = __float2bfloat16_rn(o0);
    __nv_bfloat16 h1 = __float2bfloat16_rn(o1);
    __nv_bfloat16 h2 = __float2bfloat16_rn(o2);
    __nv_bfloat16 h3 = __float2bfloat16_rn(o3);
    __nv_bfloat16 l0 = __float2bfloat16_rn(o0 - __bfloat162float(h0));
    __nv_bfloat16 l1 = __float2bfloat16_rn(o1 - __bfloat162float(h1));
    __nv_bfloat16 l2 = __float2bfloat16_rn(o2 - __bfloat162float(h2));
    __nv_bfloat16 l3 = __float2bfloat16_rn(o3 - __bfloat162float(h3));

    const size_t o = (size_t)row * PD / 2 + 2 * t;
    ((__nv_bfloat162*)hi)[o]     = __nv_bfloat162(h0, h1);
    ((__nv_bfloat162*)hi)[o + 1] = __nv_bfloat162(h2, h3);
    ((__nv_bfloat162*)lo)[o]     = __nv_bfloat162(l0, l1);
    ((__nv_bfloat162*)lo)[o + 1] = __nv_bfloat162(l2, l3);
}

// ---------------------------------------------------------------------------
// Temporal attention (att_type == 1). Reference tile quirk: feature K/V for
// attention batch b = nh*S + s comes from head-batch (b % 64).
// ---------------------------------------------------------------------------
__global__ __launch_bounds__(128)
void attn_kernel(const float* __restrict__ Q, const float* __restrict__ Kt,
                 const float* __restrict__ Vt, float* __restrict__ O)
{
    constexpr int PITCH = 129;
    __shared__ float qs[16 * PITCH];
    __shared__ float ks[17 * PITCH];
    __shared__ float vs[17 * PITCH];
    __shared__ float ps[16 * 18];

    const int s  = blockIdx.x;         // 0..195
    const int nh = blockIdx.y;         // 0..63
    const int n  = nh >> 3;
    const int h  = nh & 7;
    const int t  = threadIdx.x;        // 0..127

    const int fb = (nh * PS + s) & 63;
    const int fn = fb >> 3;
    const int fh = fb & 7;
    const size_t featKV = ((size_t)fn * PL) * PD + (size_t)fh * PHD;
    ks[t] = Kt[featKV + t];
    vs[t] = Vt[featKV + t];

    for (int f = 0; f < PF; f++) {
        const size_t r = ((size_t)n * PL + 1 + (size_t)f * PS + s) * PD + (size_t)h * PHD;
        qs[f * PITCH + t]       = Q [r + t];
        ks[(f + 1) * PITCH + t] = Kt[r + t];
        vs[(f + 1) * PITCH + t] = Vt[r + t];
    }
    __syncthreads();

    const float scale = 0.088388347648318447f;   // 1/sqrt(128)
    for (int p = t; p < 16 * 17; p += 128) {
        const int i = p / 17, j = p % 17;
        float acc = 0.f;
        #pragma unroll 8
        for (int d = 0; d < PHD; d++)
            acc = fmaf(qs[i * PITCH + d], ks[j * PITCH + d], acc);
        ps[i * 18 + j] = acc * scale;
    }
    __syncthreads();

    if (t < 16) {
        float mx = -1e30f;
        #pragma unroll
        for (int j = 0; j < 17; j++) mx = fmaxf(mx, ps[t * 18 + j]);
        float sum = 0.f;
        #pragma unroll
        for (int j = 0; j < 17; j++) {
            const float e = __expf(ps[t * 18 + j] - mx);
            ps[t * 18 + j] = e;
            sum += e;
        }
        const float inv = 1.0f / sum;
        #pragma unroll
        for (int j = 0; j < 17; j++) ps[t * 18 + j] *= inv;
    }
    __syncthreads();

    for (int i = 0; i < PF; i++) {
        float acc = 0.f;
        #pragma unroll
        for (int j = 0; j < 17; j++)
            acc = fmaf(ps[i * 18 + j], vs[j * PITCH + t], acc);
        O[((size_t)n * PL + 1 + (size_t)i * PS + s) * PD + (size_t)h * PHD + t] = acc;
    }

    if (s == 0) {
        const size_t featRow = ((size_t)n * PL) * PD + (size_t)h * PHD;
        O[featRow + t] = Q[featRow + t];
    }
}

// ---------------------------------------------------------------------------
// Launch (R7 ordering: weight transforms batched up front)
// ---------------------------------------------------------------------------
extern "C" void kernel_launch(void* const* d_in, const int* in_sizes, int n_in,
                              void* d_out, int out_size)
{
    (void)in_sizes; (void)n_in; (void)out_size;

    const float* x        = (const float*)d_in[0];
    const float* W_in     = (const float*)d_in[1];
    const float* b_in     = (const float*)d_in[2];
    const float* g_in     = (const float*)d_in[3];
    const float* beta_in  = (const float*)d_in[4];
    const float* W_q      = (const float*)d_in[5];
    const float* W_k      = (const float*)d_in[6];
    const float* W_v      = (const float*)d_in[7];
    const float* g_out    = (const float*)d_in[8];
    const float* beta_out = (const float*)d_in[9];
    const float* W_out    = (const float*)d_in[10];
    const float* b_out    = (const float*)d_in[11];
    float* out = (float*)d_out;

    float *t0, *q, *k, *v;
    __nv_bfloat16 *ahi, *alo, *wth, *wtl;
    cudaGetSymbolAddress((void**)&t0,  g_t0);
    cudaGetSymbolAddress((void**)&q,   g_q);
    cudaGetSymbolAddress((void**)&k,   g_k);
    cudaGetSymbolAddress((void**)&v,   g_v);
    cudaGetSymbolAddress((void**)&ahi, g_ahi);
    cudaGetSymbolAddress((void**)&alo, g_alo);
    cudaGetSymbolAddress((void**)&wth, g_wth);
    cudaGetSymbolAddress((void**)&wtl, g_wtl);

    cudaFuncSetAttribute(gemm_mma, cudaFuncAttributeMaxDynamicSharedMemorySize, GSMEM);

    const size_t WSLOT = 1024ull * 1024ull;
    const dim3 wsGrid(32, 32), wsBlk(32, 8);
    const int n4 = PNL * PD / 4;
    const int splitBlocks = (n4 + 255) / 256;
    const dim3 gemmGrid(8, 197);      // (N-tiles, M-tiles)
    const dim3 gemmBlk(256);

    // weight transforms (W_out deferred to overlap-neutral tail position)
    wsplit_kernel<<<wsGrid, wsBlk>>>(W_in,  wth + 0 * WSLOT, wtl + 0 * WSLOT);
    wsplit_kernel<<<wsGrid, wsBlk>>>(W_q,   wth + 1 * WSLOT, wtl + 1 * WSLOT);
    wsplit_kernel<<<wsGrid, wsBlk>>>(W_k,   wth + 2 * WSLOT, wtl + 2 * WSLOT);
    wsplit_kernel<<<wsGrid, wsBlk>>>(W_v,   wth + 3 * WSLOT, wtl + 3 * WSLOT);

    // 1. t0 = x @ W_in + b_in
    split_kernel<<<splitBlocks, 256>>>(x, ahi, alo, n4);
    gemm_mma<<<gemmGrid, gemmBlk, GSMEM>>>(PNL, ahi, alo, wth + 0 * WSLOT, wtl + 0 * WSLOT, b_in, t0);
    // 2. (ahi, alo) = split(LN(t0))
    ln_split_kernel<<<PNL, 256>>>(t0, g_in, beta_in, ahi, alo);
    // 3. q/k/v projections
    gemm_mma<<<gemmGrid, gemmBlk, GSMEM>>>(PNL, ahi, alo, wth + 1 * WSLOT, wtl + 1 * WSLOT, nullptr, q);
    gemm_mma<<<gemmGrid, gemmBlk, GSMEM>>>(PNL, ahi, alo, wth + 2 * WSLOT, wtl + 2 * WSLOT, nullptr, k);
    gemm_mma<<<gemmGrid, gemmBlk, GSMEM>>>(PNL, ahi, alo, wth + 3 * WSLOT, wtl + 3 * WSLOT, nullptr, v);
    // 4. temporal attention -> t0
    attn_kernel<<<dim3(PS, PN * PH), 128>>>(q, k, v, t0);
    // 5. (ahi, alo) = split(LN(t0))
    ln_split_kernel<<<PNL, 256>>>(t0, g_out, beta_out, ahi, alo);
    // 6. out = x1 @ W_out + b_out
    wsplit_kernel<<<wsGrid, wsBlk>>>(W_out, wth + 4 * WSLOT, wtl + 4 * WSLOT);
    gemm_mma<<<gemmGrid, gemmBlk, GSMEM>>>(PNL, ahi, alo, wth + 4 * WSLOT, wtl + 4 * WSLOT, b_out, out);
}

// round 11
// speedup vs baseline: 1.3634x; 1.3465x over previous
#include <cuda_runtime.h>
#include <cuda_fp16.h>
#include <cstdint>
#include <math.h>

// Problem constants
#define PN   8
#define PF   16
#define PS   196
#define PD   1024
#define PH   8
#define PHD  128
#define PL   (1 + PF * PS)        // 3137
#define PNL  (PN * PL)            // 25096

// ---------------------------------------------------------------------------
// Scratch (device globals)
// ---------------------------------------------------------------------------
__device__ float g_t0[(size_t)PNL * PD];
__device__ float g_q [(size_t)PNL * PD];
__device__ float g_k [(size_t)PNL * PD];
__device__ float g_v [(size_t)PNL * PD];
__device__ __half g_af [(size_t)PNL * PD];           // activations, single fp16
__device__ __half g_wth[5ull * 1024 * 1024];         // transposed weights, hi
__device__ __half g_wtl[5ull * 1024 * 1024];         // transposed weights, lo

// ---------------------------------------------------------------------------
// Helpers
// ---------------------------------------------------------------------------
__device__ __forceinline__ uint32_t smem_u32(const void* p) {
    uint32_t a;
    asm("{ .reg .u64 t; cvta.to.shared.u64 t, %1; cvt.u32.u64 %0, t; }" : "=r"(a) : "l"(p));
    return a;
}

#define LDM_X4(d0, d1, d2, d3, addr)                                             \
    asm volatile("ldmatrix.sync.aligned.m8n8.x4.shared.b16 {%0,%1,%2,%3}, [%4];" \
                 : "=r"(d0), "=r"(d1), "=r"(d2), "=r"(d3) : "r"(addr))
#define MMA_F16(d, a0, a1, a2, a3, b0, b1)                                       \
    asm volatile("mma.sync.aligned.m16n8k16.row.col.f32.f16.f16.f32 "            \
                 "{%0,%1,%2,%3}, {%4,%5,%6,%7}, {%8,%9}, {%0,%1,%2,%3};"         \
                 : "+f"((d)[0]), "+f"((d)[1]), "+f"((d)[2]), "+f"((d)[3])        \
                 : "r"(a0), "r"(a1), "r"(a2), "r"(a3), "r"(b0), "r"(b1))
#define CP_ASYNC16(dst, src, sz)                                                 \
    asm volatile("cp.async.cg.shared.global [%0], [%1], 16, %2;"                 \
                 :: "r"(dst), "l"(src), "r"(sz) : "memory")
#define CP_COMMIT()  asm volatile("cp.async.commit_group;" ::: "memory")
#define CP_WAIT_ALL() asm volatile("cp.async.wait_all;" ::: "memory")

// ---------------------------------------------------------------------------
// Convert fp32 -> fp16 (elementwise, float4 -> half2 x2)
// ---------------------------------------------------------------------------
__global__ __launch_bounds__(256)
void tohalf_kernel(const float* __restrict__ in, __half* __restrict__ o16, int n4)
{
    int i = blockIdx.x * blockDim.x + threadIdx.x;
    if (i >= n4) return;
    float4 x = ((const float4*)in)[i];
    ((__half2*)o16)[2 * i]     = __floats2half2_rn(x.x, x.y);
    ((__half2*)o16)[2 * i + 1] = __floats2half2_rn(x.z, x.w);
}

// ---------------------------------------------------------------------------
// Transpose + split weight: W[k][n] fp32 -> Wt_hi[n][k] + Wt_lo[n][k] fp16
// ---------------------------------------------------------------------------
__global__ __launch_bounds__(256)
void wsplit_kernel(const float* __restrict__ W, __half* __restrict__ hi,
                   __half* __restrict__ lo)
{
    __shared__ float t[32][33];
    const int bx = blockIdx.x, by = blockIdx.y;
    const int tx = threadIdx.x, ty = threadIdx.y;   // 32 x 8
    #pragma unroll
    for (int i = 0; i < 32; i += 8)
        t[ty + i][tx] = W[(size_t)(by * 32 + ty + i) * 1024 + bx * 32 + tx];
    __syncthreads();
    #pragma unroll
    for (int i = 0; i < 32; i += 8) {
        float v = t[tx][ty + i];
        __half h = __float2half_rn(v);
        __half l = __float2half_rn(v - __half2float(h));
        size_t o = (size_t)(bx * 32 + ty + i) * 1024 + by * 32 + tx;
        hi[o] = h;
        lo[o] = l;
    }
}

// ---------------------------------------------------------------------------
// Warp-MMA fp16 2-pass GEMM, cp.async 2-stage double buffer, 1 sync/chunk.
// C[M,1024] = A[M,1024] * Bt[1024,1024]^T (+bias)
// A single fp16 (rounding error 2^-12 rel -> ~1e-4 per GEMM); B = Bh + Bl
// fp16 pair (~exact). D = A*Bh + A*Bl, fp32 accumulate.
// Tile 128x128, BK=32; 8 warps 2(M)x4(N), each 64x32 via 4x4 m16n8k16.
// ---------------------------------------------------------------------------
#define ST 40                        // smem row stride in fp16 (80B)
#define ARR_B   (128 * ST * 2)       // bytes per array (10240)
#define STAGE_B (3 * ARR_B)          // bytes per stage (30720): A, Bh, Bl
#define GSMEM   (2 * STAGE_B)        // total dynamic smem (61440)

extern __shared__ __half dynsmem[];

__global__ __launch_bounds__(256, 2)
void gemm_mma(int M, const __half* __restrict__ aF,
              const __half* __restrict__ btHi, const __half* __restrict__ btLo,
              const float* __restrict__ bias, float* __restrict__ C)
{
    const int tid  = threadIdx.x;
    const int wid  = tid >> 5, lane = tid & 31;
    const int m0   = blockIdx.y * 128, n0 = blockIdx.x * 128;
    const int wm   = (wid >> 2) * 64;     // warp M origin
    const int wn   = (wid & 3) * 32;      // warp N origin

    const uint32_t sbase = smem_u32(dynsmem);

    float acc[4][4][4];
    #pragma unroll
    for (int mt = 0; mt < 4; mt++)
        #pragma unroll
        for (int nt = 0; nt < 4; nt++)
            #pragma unroll
            for (int e = 0; e < 4; e++) acc[mt][nt][e] = 0.0f;

    // cp.async fill: 1536 16B chunks per stage; idx = tid + i*256, i in 0..5
    // group = idx>>9 (0:A 1:Bh 2:Bl), within = idx&511, row = within>>2, c16 = within&3
    #define LOAD_STAGE(c, sb) do {                                               \
        const int kk0 = (c) * 32;                                                \
        _Pragma("unroll")                                                        \
        for (int i = 0; i < 6; i++) {                                            \
            int idx = tid + i * 256;                                             \
            int grp = idx >> 9, within = idx & 511;                              \
            int row = within >> 2, c16 = within & 3;                             \
            int kc  = kk0 + c16 * 8;                                             \
            uint32_t dst = (sb) + grp * ARR_B + (row * ST + c16 * 8) * 2;        \
            const __half* src;                                                   \
            uint32_t sz = 16;                                                    \
            if (grp == 0) {                                                      \
                int m = m0 + row;                                                \
                if (m >= M) { m = m0; sz = 0; }                                  \
                src = aF + (size_t)m * 1024 + kc;                                \
            } else {                                                             \
                src = (grp == 1 ? btHi : btLo) + (size_t)(n0 + row) * 1024 + kc; \
            }                                                                    \
            CP_ASYNC16(dst, src, sz);                                            \
        }                                                                        \
        CP_COMMIT();                                                             \
    } while (0)

    LOAD_STAGE(0, sbase);

    // ldmatrix lane addressing
    const int aRow = wm + (lane & 15);
    const int aKof = (lane >> 4) * 8;
    const int bRow = wn + (lane & 7) + ((lane >> 4) << 3);   // x4 B: 2 n-tiles
    const int bKof = ((lane >> 3) & 1) * 8;

    for (int c = 0; c < 32; c++) {
        const uint32_t cur = sbase + (c & 1) * STAGE_B;
        CP_WAIT_ALL();
        __syncthreads();                 // stage c visible; readers of (c+1)&1 done
        if (c < 31) LOAD_STAGE(c + 1, sbase + ((c + 1) & 1) * STAGE_B);

        const uint32_t Aa = cur;
        const uint32_t Bh = cur + ARR_B, Bl = cur + 2 * ARR_B;

        #pragma unroll
        for (int ks = 0; ks < 2; ks++) {
            const int kb = ks * 16;
            // B fragments (hi + lo) for the whole warp-tile (16 regs live)
            uint32_t bh[2][4], bl[2][4];
            #pragma unroll
            for (int p = 0; p < 2; p++) {
                uint32_t off = ((bRow + p * 16) * ST + kb + bKof) * 2;
                LDM_X4(bh[p][0], bh[p][1], bh[p][2], bh[p][3], Bh + off);
                LDM_X4(bl[p][0], bl[p][1], bl[p][2], bl[p][3], Bl + off);
            }
            // A fragment per mt, consumed immediately (4 regs live)
            #pragma unroll
            for (int mt = 0; mt < 4; mt++) {
                uint32_t a0, a1, a2, a3;
                uint32_t off = ((aRow + mt * 16) * ST + kb + aKof) * 2;
                LDM_X4(a0, a1, a2, a3, Aa + off);
                #pragma unroll
                for (int nt = 0; nt < 4; nt++) {
                    const int p = nt >> 1, o = (nt & 1) * 2;
                    MMA_F16(acc[mt][nt], a0, a1, a2, a3, bh[p][o], bh[p][o + 1]);
                    MMA_F16(acc[mt][nt], a0, a1, a2, a3, bl[p][o], bl[p][o + 1]);
                }
            }
        }
    }
    #undef LOAD_STAGE

    // epilogue
    const int r     = lane >> 2;
    const int cpair = (lane & 3) * 2;
    #pragma unroll
    for (int nt = 0; nt < 4; nt++) {
        const int n  = n0 + wn + nt * 8 + cpair;
        float b0 = 0.f, b1 = 0.f;
        if (bias) { b0 = bias[n]; b1 = bias[n + 1]; }
        #pragma unroll
        for (int mt = 0; mt < 4; mt++) {
            const int m = m0 + wm + mt * 16 + r;
            if (m < M) {
                float2 v0 = make_float2(acc[mt][nt][0] + b0, acc[mt][nt][1] + b1);
                *(float2*)(C + (size_t)m * 1024 + n) = v0;
            }
            if (m + 8 < M) {
                float2 v1 = make_float2(acc[mt][nt][2] + b0, acc[mt][nt][3] + b1);
                *(float2*)(C + (size_t)(m + 8) * 1024 + n) = v1;
            }
        }
    }
}

// ---------------------------------------------------------------------------
// LayerNorm over rows of 1024, output directly to fp16
// ---------------------------------------------------------------------------
__global__ __launch_bounds__(256)
void ln_half_kernel(const float* __restrict__ in, const float* __restrict__ gamma,
                    const float* __restrict__ beta, __half* __restrict__ o16)
{
    const int row = blockIdx.x;
    const int t   = threadIdx.x;
    const float4* x4 = (const float4*)(in + (size_t)row * PD);
    float4 xv = x4[t];

    float s  = xv.x + xv.y + xv.z + xv.w;
    float s2 = xv.x * xv.x + xv.y * xv.y + xv.z * xv.z + xv.w * xv.w;

    __shared__ float red[2][8];
    #pragma unroll
    for (int o = 16; o > 0; o >>= 1) {
        s  += __shfl_down_sync(0xFFFFFFFFu, s,  o);
        s2 += __shfl_down_sync(0xFFFFFFFFu, s2, o);
    }
    const int wid = t >> 5, lid = t & 31;
    if (lid == 0) { red[0][wid] = s; red[1][wid] = s2; }
    __syncthreads();
    if (wid == 0) {
        float a = (lid < 8) ? red[0][lid] : 0.f;
        float b = (lid < 8) ? red[1][lid] : 0.f;
        #pragma unroll
        for (int o = 4; o > 0; o >>= 1) {
            a += __shfl_down_sync(0xFFFFFFFFu, a, o);
            b += __shfl_down_sync(0xFFFFFFFFu, b, o);
        }
        if (lid == 0) { red[0][0] = a; red[1][0] = b; }
    }
    __syncthreads();

    const float mean = red[0][0] * (1.0f / PD);
    const float var  = red[1][0] * (1.0f / PD) - mean * mean;
    const float rstd = rsqrtf(var + 1e-5f);

    float4 gv = ((const float4*)gamma)[t];
    float4 bv = ((const float4*)beta)[t];
    float o0 = (xv.x - mean) * rstd * gv.x + bv.x;
    float o1 = (xv.y - mean) * rstd * gv.y + bv.y;
    float o2 = (xv.z - mean) * rstd * gv.z + bv.z;
    float o3 = (xv.w - mean) * rstd * gv.w + bv.w;

    const size_t o = (size_t)row * PD / 2 + 2 * t;
    ((__half2*)o16)[o]     = __floats2half2_rn(o0, o1);
    ((__half2*)o16)[o + 1] = __floats2half2_rn(o2, o3);
}

// ---------------------------------------------------------------------------
// Temporal attention (att_type == 1). Reference tile quirk: feature K/V for
// attention batch b = nh*S + s comes from head-batch (b % 64).
// ---------------------------------------------------------------------------
__global__ __launch_bounds__(128)
void attn_kernel(const float* __restrict__ Q, const float* __restrict__ Kt,
                 const float* __restrict__ Vt, float* __restrict__ O)
{
    constexpr int PITCH = 129;
    __shared__ float qs[16 * PITCH];
    __shared__ float ks[17 * PITCH];
    __shared__ float vs[17 * PITCH];
    __shared__ float ps[16 * 18];

    const int s  = blockIdx.x;         // 0..195
    const int nh = blockIdx.y;         // 0..63
    const int n  = nh >> 3;
    const int h  = nh & 7;
    const int t  = threadIdx.x;        // 0..127

    const int fb = (nh * PS + s) & 63;
    const int fn = fb >> 3;
    const int fh = fb & 7;
    const size_t featKV = ((size_t)fn * PL) * PD + (size_t)fh * PHD;
    ks[t] = Kt[featKV + t];
    vs[t] = Vt[featKV + t];

    for (int f = 0; f < PF; f++) {
        const size_t r = ((size_t)n * PL + 1 + (size_t)f * PS + s) * PD + (size_t)h * PHD;
        qs[f * PITCH + t]       = Q [r + t];
        ks[(f + 1) * PITCH + t] = Kt[r + t];
        vs[(f + 1) * PITCH + t] = Vt[r + t];
    }
    __syncthreads();

    const float scale = 0.088388347648318447f;   // 1/sqrt(128)
    for (int p = t; p < 16 * 17; p += 128) {
        const int i = p / 17, j = p % 17;
        float acc = 0.f;
        #pragma unroll 8
        for (int d = 0; d < PHD; d++)
            acc = fmaf(qs[i * PITCH + d], ks[j * PITCH + d], acc);
        ps[i * 18 + j] = acc * scale;
    }
    __syncthreads();

    if (t < 16) {
        float mx = -1e30f;
        #pragma unroll
        for (int j = 0; j < 17; j++) mx = fmaxf(mx, ps[t * 18 + j]);
        float sum = 0.f;
        #pragma unroll
        for (int j = 0; j < 17; j++) {
            const float e = __expf(ps[t * 18 + j] - mx);
            ps[t * 18 + j] = e;
            sum += e;
        }
        const float inv = 1.0f / sum;
        #pragma unroll
        for (int j = 0; j < 17; j++) ps[t * 18 + j] *= inv;
    }
    __syncthreads();

    for (int i = 0; i < PF; i++) {
        float acc = 0.f;
        #pragma unroll
        for (int j = 0; j < 17; j++)
            acc = fmaf(ps[i * 18 + j], vs[j * PITCH + t], acc);
        O[((size_t)n * PL + 1 + (size_t)i * PS + s) * PD + (size_t)h * PHD + t] = acc;
    }

    if (s == 0) {
        const size_t featRow = ((size_t)n * PL) * PD + (size_t)h * PHD;
        O[featRow + t] = Q[featRow + t];
    }
}

// ---------------------------------------------------------------------------
// Launch
// ---------------------------------------------------------------------------
extern "C" void kernel_launch(void* const* d_in, const int* in_sizes, int n_in,
                              void* d_out, int out_size)
{
    (void)in_sizes; (void)n_in; (void)out_size;

    const float* x        = (const float*)d_in[0];
    const float* W_in     = (const float*)d_in[1];
    const float* b_in     = (const float*)d_in[2];
    const float* g_in     = (const float*)d_in[3];
    const float* beta_in  = (const float*)d_in[4];
    const float* W_q      = (const float*)d_in[5];
    const float* W_k      = (const float*)d_in[6];
    const float* W_v      = (const float*)d_in[7];
    const float* g_out    = (const float*)d_in[8];
    const float* beta_out = (const float*)d_in[9];
    const float* W_out    = (const float*)d_in[10];
    const float* b_out    = (const float*)d_in[11];
    float* out = (float*)d_out;

    float *t0, *q, *k, *v;
    __half *af, *wth, *wtl;
    cudaGetSymbolAddress((void**)&t0,  g_t0);
    cudaGetSymbolAddress((void**)&q,   g_q);
    cudaGetSymbolAddress((void**)&k,   g_k);
    cudaGetSymbolAddress((void**)&v,   g_v);
    cudaGetSymbolAddress((void**)&af,  g_af);
    cudaGetSymbolAddress((void**)&wth, g_wth);
    cudaGetSymbolAddress((void**)&wtl, g_wtl);

    cudaFuncSetAttribute(gemm_mma, cudaFuncAttributeMaxDynamicSharedMemorySize, GSMEM);

    const size_t WSLOT = 1024ull * 1024ull;
    const dim3 wsGrid(32, 32), wsBlk(32, 8);
    const int n4 = PNL * PD / 4;
    const int cvtBlocks = (n4 + 255) / 256;
    const dim3 gemmGrid(8, 197);      // (N-tiles, M-tiles)
    const dim3 gemmBlk(256);

    // weight transforms (all 5 upfront)
    wsplit_kernel<<<wsGrid, wsBlk>>>(W_in,  wth + 0 * WSLOT, wtl + 0 * WSLOT);
    wsplit_kernel<<<wsGrid, wsBlk>>>(W_q,   wth + 1 * WSLOT, wtl + 1 * WSLOT);
    wsplit_kernel<<<wsGrid, wsBlk>>>(W_k,   wth + 2 * WSLOT, wtl + 2 * WSLOT);
    wsplit_kernel<<<wsGrid, wsBlk>>>(W_v,   wth + 3 * WSLOT, wtl + 3 * WSLOT);
    wsplit_kernel<<<wsGrid, wsBlk>>>(W_out, wth + 4 * WSLOT, wtl + 4 * WSLOT);

    // 1. t0 = x @ W_in + b_in
    tohalf_kernel<<<cvtBlocks, 256>>>(x, af, n4);
    gemm_mma<<<gemmGrid, gemmBlk, GSMEM>>>(PNL, af, wth + 0 * WSLOT, wtl + 0 * WSLOT, b_in, t0);
    // 2. af = fp16(LN(t0))
    ln_half_kernel<<<PNL, 256>>>(t0, g_in, beta_in, af);
    // 3. q/k/v projections
    gemm_mma<<<gemmGrid, gemmBlk, GSMEM>>>(PNL, af, wth + 1 * WSLOT, wtl + 1 * WSLOT, nullptr, q);
    gemm_mma<<<gemmGrid, gemmBlk, GSMEM>>>(PNL, af, wth + 2 * WSLOT, wtl + 2 * WSLOT, nullptr, k);
    gemm_mma<<<gemmGrid, gemmBlk, GSMEM>>>(PNL, af, wth + 3 * WSLOT, wtl + 3 * WSLOT, nullptr, v);
    // 4. temporal attention -> t0
    attn_kernel<<<dim3(PS, PN * PH), 128>>>(q, k, v, t0);
    // 5. af = fp16(LN(t0))
    ln_half_kernel<<<PNL, 256>>>(t0, g_out, beta_out, af);
    // 6. out = af @ W_out + b_out
    gemm_mma<<<gemmGrid, gemmBlk, GSMEM>>>(PNL, af, wth + 4 * WSLOT, wtl + 4 * WSLOT, b_out, out);
}

// round 12
// speedup vs baseline: 2.0391x; 1.4957x over previous
#include <cuda_runtime.h>
#include <cuda_fp16.h>
#include <cstdint>
#include <math.h>

// Problem constants
#define PN   8
#define PF   16
#define PS   196
#define PD   1024
#define PH   8
#define PHD  128
#define PL   (1 + PF * PS)        // 3137
#define PNL  (PN * PL)            // 25096

// ---------------------------------------------------------------------------
// Scratch (device globals)
// ---------------------------------------------------------------------------
__device__ float g_t0[(size_t)PNL * PD];
__device__ float g_q [(size_t)PNL * PD];
__device__ float g_k [(size_t)PNL * PD];
__device__ float g_v [(size_t)PNL * PD];
__device__ __half g_af [(size_t)PNL * PD];           // activations, fp16
__device__ __half g_wt [5ull * 1024 * 1024];         // transposed weights, fp16

// ---------------------------------------------------------------------------
// Helpers
// ---------------------------------------------------------------------------
__device__ __forceinline__ uint32_t smem_u32(const void* p) {
    uint32_t a;
    asm("{ .reg .u64 t; cvta.to.shared.u64 t, %1; cvt.u32.u64 %0, t; }" : "=r"(a) : "l"(p));
    return a;
}

#define LDM_X4(d0, d1, d2, d3, addr)                                             \
    asm volatile("ldmatrix.sync.aligned.m8n8.x4.shared.b16 {%0,%1,%2,%3}, [%4];" \
                 : "=r"(d0), "=r"(d1), "=r"(d2), "=r"(d3) : "r"(addr))
#define MMA_F16(d, a0, a1, a2, a3, b0, b1)                                       \
    asm volatile("mma.sync.aligned.m16n8k16.row.col.f32.f16.f16.f32 "            \
                 "{%0,%1,%2,%3}, {%4,%5,%6,%7}, {%8,%9}, {%0,%1,%2,%3};"         \
                 : "+f"((d)[0]), "+f"((d)[1]), "+f"((d)[2]), "+f"((d)[3])        \
                 : "r"(a0), "r"(a1), "r"(a2), "r"(a3), "r"(b0), "r"(b1))
#define CP_ASYNC16(dst, src, sz)                                                 \
    asm volatile("cp.async.cg.shared.global [%0], [%1], 16, %2;"                 \
                 :: "r"(dst), "l"(src), "r"(sz) : "memory")
#define CP_COMMIT()  asm volatile("cp.async.commit_group;" ::: "memory")
#define CP_WAIT_ALL() asm volatile("cp.async.wait_all;" ::: "memory")

// ---------------------------------------------------------------------------
// Convert fp32 -> fp16 (elementwise)
// ---------------------------------------------------------------------------
__global__ __launch_bounds__(256)
void tohalf_kernel(const float* __restrict__ in, __half* __restrict__ o16, int n4)
{
    int i = blockIdx.x * blockDim.x + threadIdx.x;
    if (i >= n4) return;
    float4 x = ((const float4*)in)[i];
    ((__half2*)o16)[2 * i]     = __floats2half2_rn(x.x, x.y);
    ((__half2*)o16)[2 * i + 1] = __floats2half2_rn(x.z, x.w);
}

// ---------------------------------------------------------------------------
// Transpose weight: W[k][n] fp32 -> Wt[n][k] fp16
// ---------------------------------------------------------------------------
__global__ __launch_bounds__(256)
void wtrans_kernel(const float* __restrict__ W, __half* __restrict__ o16)
{
    __shared__ float t[32][33];
    const int bx = blockIdx.x, by = blockIdx.y;
    const int tx = threadIdx.x, ty = threadIdx.y;   // 32 x 8
    #pragma unroll
    for (int i = 0; i < 32; i += 8)
        t[ty + i][tx] = W[(size_t)(by * 32 + ty + i) * 1024 + bx * 32 + tx];
    __syncthreads();
    #pragma unroll
    for (int i = 0; i < 32; i += 8) {
        size_t o = (size_t)(bx * 32 + ty + i) * 1024 + by * 32 + tx;
        o16[o] = __float2half_rn(t[tx][ty + i]);
    }
}

// ---------------------------------------------------------------------------
// Warp-MMA fp16 1-pass GEMM, cp.async 2-stage double buffer, 1 sync/chunk.
// C[M,1024] = A[M,1024] * Bt[1024,1024]^T (+bias), fp32 accumulate.
// Tile 128x128, BK=32; 8 warps 2(M)x4(N), each 64x32 via 4x4 m16n8k16.
// ---------------------------------------------------------------------------
#define ST 40                        // smem row stride in fp16 (80B)
#define ARR_B   (128 * ST * 2)       // bytes per array (10240)
#define STAGE_B (2 * ARR_B)          // bytes per stage (20480): A, B
#define GSMEM   (2 * STAGE_B)        // total dynamic smem (40960)

extern __shared__ __half dynsmem[];

__global__ __launch_bounds__(256, 2)
void gemm_mma(int M, const __half* __restrict__ aF, const __half* __restrict__ bT,
              const float* __restrict__ bias, float* __restrict__ C)
{
    const int tid  = threadIdx.x;
    const int wid  = tid >> 5, lane = tid & 31;
    const int m0   = blockIdx.y * 128, n0 = blockIdx.x * 128;
    const int wm   = (wid >> 2) * 64;     // warp M origin
    const int wn   = (wid & 3) * 32;      // warp N origin

    const uint32_t sbase = smem_u32(dynsmem);

    float acc[4][4][4];
    #pragma unroll
    for (int mt = 0; mt < 4; mt++)
        #pragma unroll
        for (int nt = 0; nt < 4; nt++)
            #pragma unroll
            for (int e = 0; e < 4; e++) acc[mt][nt][e] = 0.0f;

    // cp.async fill: 1024 16B chunks per stage; idx = tid + i*256, i in 0..3
    // group = idx>>9 (0:A 1:B), within = idx&511, row = within>>2, c16 = within&3
    #define LOAD_STAGE(c, sb) do {                                               \
        const int kk0 = (c) * 32;                                                \
        _Pragma("unroll")                                                        \
        for (int i = 0; i < 4; i++) {                                            \
            int idx = tid + i * 256;                                             \
            int grp = idx >> 9, within = idx & 511;                              \
            int row = within >> 2, c16 = within & 3;                             \
            int kc  = kk0 + c16 * 8;                                             \
            uint32_t dst = (sb) + grp * ARR_B + (row * ST + c16 * 8) * 2;        \
            const __half* src;                                                   \
            uint32_t sz = 16;                                                    \
            if (grp == 0) {                                                      \
                int m = m0 + row;                                                \
                if (m >= M) { m = m0; sz = 0; }                                  \
                src = aF + (size_t)m * 1024 + kc;                                \
            } else {                                                             \
                src = bT + (size_t)(n0 + row) * 1024 + kc;                       \
            }                                                                    \
            CP_ASYNC16(dst, src, sz);                                            \
        }                                                                        \
        CP_COMMIT();                                                             \
    } while (0)

    LOAD_STAGE(0, sbase);

    // ldmatrix lane addressing
    const int aRow = wm + (lane & 15);
    const int aKof = (lane >> 4) * 8;
    const int bRow = wn + (lane & 7) + ((lane >> 4) << 3);   // x4 B: 2 n-tiles
    const int bKof = ((lane >> 3) & 1) * 8;

    for (int c = 0; c < 32; c++) {
        const uint32_t cur = sbase + (c & 1) * STAGE_B;
        CP_WAIT_ALL();
        __syncthreads();                 // stage c visible; readers of (c+1)&1 done
        if (c < 31) LOAD_STAGE(c + 1, sbase + ((c + 1) & 1) * STAGE_B);

        const uint32_t Aa = cur, Bb = cur + ARR_B;

        #pragma unroll
        for (int ks = 0; ks < 2; ks++) {
            const int kb = ks * 16;
            // B fragments for the whole warp-tile (8 regs live)
            uint32_t bf[2][4];
            #pragma unroll
            for (int p = 0; p < 2; p++) {
                uint32_t off = ((bRow + p * 16) * ST + kb + bKof) * 2;
                LDM_X4(bf[p][0], bf[p][1], bf[p][2], bf[p][3], Bb + off);
            }
            // A fragment per mt, consumed immediately (4 regs live)
            #pragma unroll
            for (int mt = 0; mt < 4; mt++) {
                uint32_t a0, a1, a2, a3;
                uint32_t off = ((aRow + mt * 16) * ST + kb + aKof) * 2;
                LDM_X4(a0, a1, a2, a3, Aa + off);
                #pragma unroll
                for (int nt = 0; nt < 4; nt++) {
                    const int p = nt >> 1, o = (nt & 1) * 2;
                    MMA_F16(acc[mt][nt], a0, a1, a2, a3, bf[p][o], bf[p][o + 1]);
                }
            }
        }
    }
    #undef LOAD_STAGE

    // epilogue
    const int r     = lane >> 2;
    const int cpair = (lane & 3) * 2;
    #pragma unroll
    for (int nt = 0; nt < 4; nt++) {
        const int n  = n0 + wn + nt * 8 + cpair;
        float b0 = 0.f, b1 = 0.f;
        if (bias) { b0 = bias[n]; b1 = bias[n + 1]; }
        #pragma unroll
        for (int mt = 0; mt < 4; mt++) {
            const int m = m0 + wm + mt * 16 + r;
            if (m < M) {
                float2 v0 = make_float2(acc[mt][nt][0] + b0, acc[mt][nt][1] + b1);
                *(float2*)(C + (size_t)m * 1024 + n) = v0;
            }
            if (m + 8 < M) {
                float2 v1 = make_float2(acc[mt][nt][2] + b0, acc[mt][nt][3] + b1);
                *(float2*)(C + (size_t)(m + 8) * 1024 + n) = v1;
            }
        }
    }
}

// ---------------------------------------------------------------------------
// LayerNorm over rows of 1024, output directly to fp16
// ---------------------------------------------------------------------------
__global__ __launch_bounds__(256)
void ln_half_kernel(const float* __restrict__ in, const float* __restrict__ gamma,
                    const float* __restrict__ beta, __half* __restrict__ o16)
{
    const int row = blockIdx.x;
    const int t   = threadIdx.x;
    const float4* x4 = (const float4*)(in + (size_t)row * PD);
    float4 xv = x4[t];

    float s  = xv.x + xv.y + xv.z + xv.w;
    float s2 = xv.x * xv.x + xv.y * xv.y + xv.z * xv.z + xv.w * xv.w;

    __shared__ float red[2][8];
    #pragma unroll
    for (int o = 16; o > 0; o >>= 1) {
        s  += __shfl_down_sync(0xFFFFFFFFu, s,  o);
        s2 += __shfl_down_sync(0xFFFFFFFFu, s2, o);
    }
    const int wid = t >> 5, lid = t & 31;
    if (lid == 0) { red[0][wid] = s; red[1][wid] = s2; }
    __syncthreads();
    if (wid == 0) {
        float a = (lid < 8) ? red[0][lid] : 0.f;
        float b = (lid < 8) ? red[1][lid] : 0.f;
        #pragma unroll
        for (int o = 4; o > 0; o >>= 1) {
            a += __shfl_down_sync(0xFFFFFFFFu, a, o);
            b += __shfl_down_sync(0xFFFFFFFFu, b, o);
        }
        if (lid == 0) { red[0][0] = a; red[1][0] = b; }
    }
    __syncthreads();

    const float mean = red[0][0] * (1.0f / PD);
    const float var  = red[1][0] * (1.0f / PD) - mean * mean;
    const float rstd = rsqrtf(var + 1e-5f);

    float4 gv = ((const float4*)gamma)[t];
    float4 bv = ((const float4*)beta)[t];
    float o0 = (xv.x - mean) * rstd * gv.x + bv.x;
    float o1 = (xv.y - mean) * rstd * gv.y + bv.y;
    float o2 = (xv.z - mean) * rstd * gv.z + bv.z;
    float o3 = (xv.w - mean) * rstd * gv.w + bv.w;

    const size_t o = (size_t)row * PD / 2 + 2 * t;
    ((__half2*)o16)[o]     = __floats2half2_rn(o0, o1);
    ((__half2*)o16)[o + 1] = __floats2half2_rn(o2, o3);
}

// ---------------------------------------------------------------------------
// Temporal attention (att_type == 1). Reference tile quirk: feature K/V for
// attention batch b = nh*S + s comes from head-batch (b % 64).
// ---------------------------------------------------------------------------
__global__ __launch_bounds__(128)
void attn_kernel(const float* __restrict__ Q, const float* __restrict__ Kt,
                 const float* __restrict__ Vt, float* __restrict__ O)
{
    constexpr int PITCH = 129;
    __shared__ float qs[16 * PITCH];
    __shared__ float ks[17 * PITCH];
    __shared__ float vs[17 * PITCH];
    __shared__ float ps[16 * 18];

    const int s  = blockIdx.x;         // 0..195
    const int nh = blockIdx.y;         // 0..63
    const int n  = nh >> 3;
    const int h  = nh & 7;
    const int t  = threadIdx.x;        // 0..127

    const int fb = (nh * PS + s) & 63;
    const int fn = fb >> 3;
    const int fh = fb & 7;
    const size_t featKV = ((size_t)fn * PL) * PD + (size_t)fh * PHD;
    ks[t] = Kt[featKV + t];
    vs[t] = Vt[featKV + t];

    for (int f = 0; f < PF; f++) {
        const size_t r = ((size_t)n * PL + 1 + (size_t)f * PS + s) * PD + (size_t)h * PHD;
        qs[f * PITCH + t]       = Q [r + t];
        ks[(f + 1) * PITCH + t] = Kt[r + t];
        vs[(f + 1) * PITCH + t] = Vt[r + t];
    }
    __syncthreads();

    const float scale = 0.088388347648318447f;   // 1/sqrt(128)
    for (int p = t; p < 16 * 17; p += 128) {
        const int i = p / 17, j = p % 17;
        float acc = 0.f;
        #pragma unroll 8
        for (int d = 0; d < PHD; d++)
            acc = fmaf(qs[i * PITCH + d], ks[j * PITCH + d], acc);
        ps[i * 18 + j] = acc * scale;
    }
    __syncthreads();

    if (t < 16) {
        float mx = -1e30f;
        #pragma unroll
        for (int j = 0; j < 17; j++) mx = fmaxf(mx, ps[t * 18 + j]);
        float sum = 0.f;
        #pragma unroll
        for (int j = 0; j < 17; j++) {
            const float e = __expf(ps[t * 18 + j] - mx);
            ps[t * 18 + j] = e;
            sum += e;
        }
        const float inv = 1.0f / sum;
        #pragma unroll
        for (int j = 0; j < 17; j++) ps[t * 18 + j] *= inv;
    }
    __syncthreads();

    for (int i = 0; i < PF; i++) {
        float acc = 0.f;
        #pragma unroll
        for (int j = 0; j < 17; j++)
            acc = fmaf(ps[i * 18 + j], vs[j * PITCH + t], acc);
        O[((size_t)n * PL + 1 + (size_t)i * PS + s) * PD + (size_t)h * PHD + t] = acc;
    }

    if (s == 0) {
        const size_t featRow = ((size_t)n * PL) * PD + (size_t)h * PHD;
        O[featRow + t] = Q[featRow + t];
    }
}

// ---------------------------------------------------------------------------
// Launch
// ---------------------------------------------------------------------------
extern "C" void kernel_launch(void* const* d_in, const int* in_sizes, int n_in,
                              void* d_out, int out_size)
{
    (void)in_sizes; (void)n_in; (void)out_size;

    const float* x        = (const float*)d_in[0];
    const float* W_in     = (const float*)d_in[1];
    const float* b_in     = (const float*)d_in[2];
    const float* g_in     = (const float*)d_in[3];
    const float* beta_in  = (const float*)d_in[4];
    const float* W_q      = (const float*)d_in[5];
    const float* W_k      = (const float*)d_in[6];
    const float* W_v      = (const float*)d_in[7];
    const float* g_out    = (const float*)d_in[8];
    const float* beta_out = (const float*)d_in[9];
    const float* W_out    = (const float*)d_in[10];
    const float* b_out    = (const float*)d_in[11];
    float* out = (float*)d_out;

    float *t0, *q, *k, *v;
    __half *af, *wt;
    cudaGetSymbolAddress((void**)&t0,  g_t0);
    cudaGetSymbolAddress((void**)&q,   g_q);
    cudaGetSymbolAddress((void**)&k,   g_k);
    cudaGetSymbolAddress((void**)&v,   g_v);
    cudaGetSymbolAddress((void**)&af,  g_af);
    cudaGetSymbolAddress((void**)&wt,  g_wt);

    cudaFuncSetAttribute(gemm_mma, cudaFuncAttributeMaxDynamicSharedMemorySize, GSMEM);

    const size_t WSLOT = 1024ull * 1024ull;
    const dim3 wsGrid(32, 32), wsBlk(32, 8);
    const int n4 = PNL * PD / 4;
    const int cvtBlocks = (n4 + 255) / 256;
    const dim3 gemmGrid(8, 197);      // (N-tiles, M-tiles)
    const dim3 gemmBlk(256);

    // weight transforms (all 5 upfront)
    wtrans_kernel<<<wsGrid, wsBlk>>>(W_in,  wt + 0 * WSLOT);
    wtrans_kernel<<<wsGrid, wsBlk>>>(W_q,   wt + 1 * WSLOT);
    wtrans_kernel<<<wsGrid, wsBlk>>>(W_k,   wt + 2 * WSLOT);
    wtrans_kernel<<<wsGrid, wsBlk>>>(W_v,   wt + 3 * WSLOT);
    wtrans_kernel<<<wsGrid, wsBlk>>>(W_out, wt + 4 * WSLOT);

    // 1. t0 = x @ W_in + b_in
    tohalf_kernel<<<cvtBlocks, 256>>>(x, af, n4);
    gemm_mma<<<gemmGrid, gemmBlk, GSMEM>>>(PNL, af, wt + 0 * WSLOT, b_in, t0);
    // 2. af = fp16(LN(t0))
    ln_half_kernel<<<PNL, 256>>>(t0, g_in, beta_in, af);
    // 3. q/k/v projections
    gemm_mma<<<gemmGrid, gemmBlk, GSMEM>>>(PNL, af, wt + 1 * WSLOT, nullptr, q);
    gemm_mma<<<gemmGrid, gemmBlk, GSMEM>>>(PNL, af, wt + 2 * WSLOT, nullptr, k);
    gemm_mma<<<gemmGrid, gemmBlk, GSMEM>>>(PNL, af, wt + 3 * WSLOT, nullptr, v);
    // 4. temporal attention -> t0
    attn_kernel<<<dim3(PS, PN * PH), 128>>>(q, k, v, t0);
    // 5. af = fp16(LN(t0))
    ln_half_kernel<<<PNL, 256>>>(t0, g_out, beta_out, af);
    // 6. out = af @ W_out + b_out
    gemm_mma<<<gemmGrid, gemmBlk, GSMEM>>>(PNL, af, wt + 4 * WSLOT, b_out, out);
}

// round 13
// speedup vs baseline: 2.1370x; 1.0480x over previous
#include <cuda_runtime.h>
#include <cuda_fp16.h>
#include <cstdint>
#include <math.h>

// Problem constants
#define PN   8
#define PF   16
#define PS   196
#define PD   1024
#define PH   8
#define PHD  128
#define PL   (1 + PF * PS)        // 3137
#define PNL  (PN * PL)            // 25096

// ---------------------------------------------------------------------------
// Scratch (device globals)
// ---------------------------------------------------------------------------
__device__ float g_t0[(size_t)PNL * PD];
__device__ __half g_qh[(size_t)PNL * PD];
__device__ __half g_kh[(size_t)PNL * PD];
__device__ __half g_vh[(size_t)PNL * PD];
__device__ __half g_af[(size_t)PNL * PD];            // activations, fp16
__device__ __half g_wt[5ull * 1024 * 1024];          // transposed weights, fp16

// ---------------------------------------------------------------------------
// Helpers
// ---------------------------------------------------------------------------
__device__ __forceinline__ uint32_t smem_u32(const void* p) {
    uint32_t a;
    asm("{ .reg .u64 t; cvta.to.shared.u64 t, %1; cvt.u32.u64 %0, t; }" : "=r"(a) : "l"(p));
    return a;
}

#define LDM_X4(d0, d1, d2, d3, addr)                                             \
    asm volatile("ldmatrix.sync.aligned.m8n8.x4.shared.b16 {%0,%1,%2,%3}, [%4];" \
                 : "=r"(d0), "=r"(d1), "=r"(d2), "=r"(d3) : "r"(addr))
#define MMA_F16(d, a0, a1, a2, a3, b0, b1)                                       \
    asm volatile("mma.sync.aligned.m16n8k16.row.col.f32.f16.f16.f32 "            \
                 "{%0,%1,%2,%3}, {%4,%5,%6,%7}, {%8,%9}, {%0,%1,%2,%3};"         \
                 : "+f"((d)[0]), "+f"((d)[1]), "+f"((d)[2]), "+f"((d)[3])        \
                 : "r"(a0), "r"(a1), "r"(a2), "r"(a3), "r"(b0), "r"(b1))
#define CP_ASYNC16(dst, src, sz)                                                 \
    asm volatile("cp.async.cg.shared.global [%0], [%1], 16, %2;"                 \
                 :: "r"(dst), "l"(src), "r"(sz) : "memory")
#define CP_COMMIT()  asm volatile("cp.async.commit_group;" ::: "memory")
#define CP_WAIT_ALL() asm volatile("cp.async.wait_all;" ::: "memory")

// ---------------------------------------------------------------------------
// Convert fp32 -> fp16 (elementwise)
// ---------------------------------------------------------------------------
__global__ __launch_bounds__(256)
void tohalf_kernel(const float* __restrict__ in, __half* __restrict__ o16, int n4)
{
    int i = blockIdx.x * blockDim.x + threadIdx.x;
    if (i >= n4) return;
    float4 x = ((const float4*)in)[i];
    ((__half2*)o16)[2 * i]     = __floats2half2_rn(x.x, x.y);
    ((__half2*)o16)[2 * i + 1] = __floats2half2_rn(x.z, x.w);
}

// ---------------------------------------------------------------------------
// Transpose weight: W[k][n] fp32 -> Wt[n][k] fp16
// ---------------------------------------------------------------------------
__global__ __launch_bounds__(256)
void wtrans_kernel(const float* __restrict__ W, __half* __restrict__ o16)
{
    __shared__ float t[32][33];
    const int bx = blockIdx.x, by = blockIdx.y;
    const int tx = threadIdx.x, ty = threadIdx.y;   // 32 x 8
    #pragma unroll
    for (int i = 0; i < 32; i += 8)
        t[ty + i][tx] = W[(size_t)(by * 32 + ty + i) * 1024 + bx * 32 + tx];
    __syncthreads();
    #pragma unroll
    for (int i = 0; i < 32; i += 8) {
        size_t o = (size_t)(bx * 32 + ty + i) * 1024 + by * 32 + tx;
        o16[o] = __float2half_rn(t[tx][ty + i]);
    }
}

// ---------------------------------------------------------------------------
// Shared fp16 warp-MMA mainloop: 128x128 tile at (m0, n0), BK=32, 2-stage
// cp.async double buffer, 1 sync/chunk. Accumulates into acc[4][4][4].
// ---------------------------------------------------------------------------
#define ST 40                        // smem row stride in fp16 (80B)
#define ARR_B   (128 * ST * 2)       // bytes per array (10240)
#define STAGE_B (2 * ARR_B)          // bytes per stage (20480): A, B
#define GSMEM   (2 * STAGE_B)        // total dynamic smem (40960)

extern __shared__ __half dynsmem[];

__device__ __forceinline__ void gemm_mainloop(
    int M, const __half* __restrict__ aF, const __half* __restrict__ bT,
    int m0, int n0, int tid, int wid, int lane, float acc[4][4][4])
{
    const int wm = (wid >> 2) * 64;
    const int wn = (wid & 3) * 32;
    const uint32_t sbase = smem_u32(dynsmem);

    #define LOAD_STAGE(c, sb) do {                                               \
        const int kk0 = (c) * 32;                                                \
        _Pragma("unroll")                                                        \
        for (int i = 0; i < 4; i++) {                                            \
            int idx = tid + i * 256;                                             \
            int grp = idx >> 9, within = idx & 511;                              \
            int row = within >> 2, c16 = within & 3;                             \
            int kc  = kk0 + c16 * 8;                                             \
            uint32_t dst = (sb) + grp * ARR_B + (row * ST + c16 * 8) * 2;        \
            const __half* src;                                                   \
            uint32_t sz = 16;                                                    \
            if (grp == 0) {                                                      \
                int m = m0 + row;                                                \
                if (m >= M) { m = m0; sz = 0; }                                  \
                src = aF + (size_t)m * 1024 + kc;                                \
            } else {                                                             \
                src = bT + (size_t)(n0 + row) * 1024 + kc;                       \
            }                                                                    \
            CP_ASYNC16(dst, src, sz);                                            \
        }                                                                        \
        CP_COMMIT();                                                             \
    } while (0)

    LOAD_STAGE(0, sbase);

    const int aRow = wm + (lane & 15);
    const int aKof = (lane >> 4) * 8;
    const int bRow = wn + (lane & 7) + ((lane >> 4) << 3);
    const int bKof = ((lane >> 3) & 1) * 8;

    for (int c = 0; c < 32; c++) {
        const uint32_t cur = sbase + (c & 1) * STAGE_B;
        CP_WAIT_ALL();
        __syncthreads();
        if (c < 31) LOAD_STAGE(c + 1, sbase + ((c + 1) & 1) * STAGE_B);

        const uint32_t Aa = cur, Bb = cur + ARR_B;

        #pragma unroll
        for (int ks = 0; ks < 2; ks++) {
            const int kb = ks * 16;
            uint32_t bf[2][4];
            #pragma unroll
            for (int p = 0; p < 2; p++) {
                uint32_t off = ((bRow + p * 16) * ST + kb + bKof) * 2;
                LDM_X4(bf[p][0], bf[p][1], bf[p][2], bf[p][3], Bb + off);
            }
            #pragma unroll
            for (int mt = 0; mt < 4; mt++) {
                uint32_t a0, a1, a2, a3;
                uint32_t off = ((aRow + mt * 16) * ST + kb + aKof) * 2;
                LDM_X4(a0, a1, a2, a3, Aa + off);
                #pragma unroll
                for (int nt = 0; nt < 4; nt++) {
                    const int p = nt >> 1, o = (nt & 1) * 2;
                    MMA_F16(acc[mt][nt], a0, a1, a2, a3, bf[p][o], bf[p][o + 1]);
                }
            }
        }
    }
    #undef LOAD_STAGE
}

// ---------------------------------------------------------------------------
// fp32-output GEMM (+bias): used for W_in and W_out
// ---------------------------------------------------------------------------
__global__ __launch_bounds__(256, 2)
void gemm_f32(int M, const __half* __restrict__ aF, const __half* __restrict__ bT,
              const float* __restrict__ bias, float* __restrict__ C)
{
    const int tid = threadIdx.x, wid = tid >> 5, lane = tid & 31;
    const int m0 = blockIdx.y * 128, n0 = blockIdx.x * 128;

    float acc[4][4][4];
    #pragma unroll
    for (int mt = 0; mt < 4; mt++)
        #pragma unroll
        for (int nt = 0; nt < 4; nt++)
            #pragma unroll
            for (int e = 0; e < 4; e++) acc[mt][nt][e] = 0.0f;

    gemm_mainloop(M, aF, bT, m0, n0, tid, wid, lane, acc);

    const int wm = (wid >> 2) * 64, wn = (wid & 3) * 32;
    const int r = lane >> 2, cpair = (lane & 3) * 2;
    #pragma unroll
    for (int nt = 0; nt < 4; nt++) {
        const int n = n0 + wn + nt * 8 + cpair;
        float b0 = 0.f, b1 = 0.f;
        if (bias) { b0 = bias[n]; b1 = bias[n + 1]; }
        #pragma unroll
        for (int mt = 0; mt < 4; mt++) {
            const int m = m0 + wm + mt * 16 + r;
            if (m < M)
                *(float2*)(C + (size_t)m * 1024 + n) =
                    make_float2(acc[mt][nt][0] + b0, acc[mt][nt][1] + b1);
            if (m + 8 < M)
                *(float2*)(C + (size_t)(m + 8) * 1024 + n) =
                    make_float2(acc[mt][nt][2] + b0, acc[mt][nt][3] + b1);
        }
    }
}

// ---------------------------------------------------------------------------
// Fused QKV GEMM: N=3072 (weight slots 1-3 contiguous), fp16 outputs into
// q/k/v arrays selected by n0>>10. No bias.
// ---------------------------------------------------------------------------
__global__ __launch_bounds__(256, 2)
void gemm_qkv(int M, const __half* __restrict__ aF, const __half* __restrict__ bT,
              __half* __restrict__ q, __half* __restrict__ k, __half* __restrict__ v)
{
    const int tid = threadIdx.x, wid = tid >> 5, lane = tid & 31;
    const int m0 = blockIdx.y * 128, n0 = blockIdx.x * 128;   // n0 in [0,3072)

    float acc[4][4][4];
    #pragma unroll
    for (int mt = 0; mt < 4; mt++)
        #pragma unroll
        for (int nt = 0; nt < 4; nt++)
            #pragma unroll
            for (int e = 0; e < 4; e++) acc[mt][nt][e] = 0.0f;

    gemm_mainloop(M, aF, bT, m0, n0, tid, wid, lane, acc);

    __half* C = (n0 < 1024) ? q : (n0 < 2048 ? k : v);
    const int nb = n0 & 1023;

    const int wm = (wid >> 2) * 64, wn = (wid & 3) * 32;
    const int r = lane >> 2, cpair = (lane & 3) * 2;
    #pragma unroll
    for (int nt = 0; nt < 4; nt++) {
        const int n = nb + wn + nt * 8 + cpair;
        #pragma unroll
        for (int mt = 0; mt < 4; mt++) {
            const int m = m0 + wm + mt * 16 + r;
            if (m < M)
                *(__half2*)(C + (size_t)m * 1024 + n) =
                    __floats2half2_rn(acc[mt][nt][0], acc[mt][nt][1]);
            if (m + 8 < M)
                *(__half2*)(C + (size_t)(m + 8) * 1024 + n) =
                    __floats2half2_rn(acc[mt][nt][2], acc[mt][nt][3]);
        }
    }
}

// ---------------------------------------------------------------------------
// LayerNorm over rows of 1024, output directly to fp16
// ---------------------------------------------------------------------------
__global__ __launch_bounds__(256)
void ln_half_kernel(const float* __restrict__ in, const float* __restrict__ gamma,
                    const float* __restrict__ beta, __half* __restrict__ o16)
{
    const int row = blockIdx.x;
    const int t   = threadIdx.x;
    const float4* x4 = (const float4*)(in + (size_t)row * PD);
    float4 xv = x4[t];

    float s  = xv.x + xv.y + xv.z + xv.w;
    float s2 = xv.x * xv.x + xv.y * xv.y + xv.z * xv.z + xv.w * xv.w;

    __shared__ float red[2][8];
    #pragma unroll
    for (int o = 16; o > 0; o >>= 1) {
        s  += __shfl_down_sync(0xFFFFFFFFu, s,  o);
        s2 += __shfl_down_sync(0xFFFFFFFFu, s2, o);
    }
    const int wid = t >> 5, lid = t & 31;
    if (lid == 0) { red[0][wid] = s; red[1][wid] = s2; }
    __syncthreads();
    if (wid == 0) {
        float a = (lid < 8) ? red[0][lid] : 0.f;
        float b = (lid < 8) ? red[1][lid] : 0.f;
        #pragma unroll
        for (int o = 4; o > 0; o >>= 1) {
            a += __shfl_down_sync(0xFFFFFFFFu, a, o);
            b += __shfl_down_sync(0xFFFFFFFFu, b, o);
        }
        if (lid == 0) { red[0][0] = a; red[1][0] = b; }
    }
    __syncthreads();

    const float mean = red[0][0] * (1.0f / PD);
    const float var  = red[1][0] * (1.0f / PD) - mean * mean;
    const float rstd = rsqrtf(var + 1e-5f);

    float4 gv = ((const float4*)gamma)[t];
    float4 bv = ((const float4*)beta)[t];
    float o0 = (xv.x - mean) * rstd * gv.x + bv.x;
    float o1 = (xv.y - mean) * rstd * gv.y + bv.y;
    float o2 = (xv.z - mean) * rstd * gv.z + bv.z;
    float o3 = (xv.w - mean) * rstd * gv.w + bv.w;

    const size_t o = (size_t)row * PD / 2 + 2 * t;
    ((__half2*)o16)[o]     = __floats2half2_rn(o0, o1);
    ((__half2*)o16)[o + 1] = __floats2half2_rn(o2, o3);
}

// ---------------------------------------------------------------------------
// Temporal attention (att_type == 1), fp16 q/k/v inputs, fp32 compute.
// Reference tile quirk: feature K/V for attention batch b = nh*S + s comes
// from head-batch (b % 64).
// ---------------------------------------------------------------------------
__global__ __launch_bounds__(128)
void attn_kernel(const __half* __restrict__ Q, const __half* __restrict__ Kt,
                 const __half* __restrict__ Vt, float* __restrict__ O)
{
    constexpr int PITCH = 129;
    __shared__ float qs[16 * PITCH];
    __shared__ float ks[17 * PITCH];
    __shared__ float vs[17 * PITCH];
    __shared__ float ps[16 * 18];

    const int s  = blockIdx.x;         // 0..195
    const int nh = blockIdx.y;         // 0..63
    const int n  = nh >> 3;
    const int h  = nh & 7;
    const int t  = threadIdx.x;        // 0..127

    const int fb = (nh * PS + s) & 63;
    const int fn = fb >> 3;
    const int fh = fb & 7;
    const size_t featKV = ((size_t)fn * PL) * PD + (size_t)fh * PHD;
    ks[t] = __half2float(Kt[featKV + t]);
    vs[t] = __half2float(Vt[featKV + t]);

    for (int f = 0; f < PF; f++) {
        const size_t r = ((size_t)n * PL + 1 + (size_t)f * PS + s) * PD + (size_t)h * PHD;
        qs[f * PITCH + t]       = __half2float(Q [r + t]);
        ks[(f + 1) * PITCH + t] = __half2float(Kt[r + t]);
        vs[(f + 1) * PITCH + t] = __half2float(Vt[r + t]);
    }
    __syncthreads();

    const float scale = 0.088388347648318447f;   // 1/sqrt(128)
    for (int p = t; p < 16 * 17; p += 128) {
        const int i = p / 17, j = p % 17;
        float acc = 0.f;
        #pragma unroll 8
        for (int d = 0; d < PHD; d++)
            acc = fmaf(qs[i * PITCH + d], ks[j * PITCH + d], acc);
        ps[i * 18 + j] = acc * scale;
    }
    __syncthreads();

    if (t < 16) {
        float mx = -1e30f;
        #pragma unroll
        for (int j = 0; j < 17; j++) mx = fmaxf(mx, ps[t * 18 + j]);
        float sum = 0.f;
        #pragma unroll
        for (int j = 0; j < 17; j++) {
            const float e = __expf(ps[t * 18 + j] - mx);
            ps[t * 18 + j] = e;
            sum += e;
        }
        const float inv = 1.0f / sum;
        #pragma unroll
        for (int j = 0; j < 17; j++) ps[t * 18 + j] *= inv;
    }
    __syncthreads();

    for (int i = 0; i < PF; i++) {
        float acc = 0.f;
        #pragma unroll
        for (int j = 0; j < 17; j++)
            acc = fmaf(ps[i * 18 + j], vs[j * PITCH + t], acc);
        O[((size_t)n * PL + 1 + (size_t)i * PS + s) * PD + (size_t)h * PHD + t] = acc;
    }

    if (s == 0) {
        const size_t featRow = ((size_t)n * PL) * PD + (size_t)h * PHD;
        O[featRow + t] = __half2float(Q[featRow + t]);
    }
}

// ---------------------------------------------------------------------------
// Launch
// ---------------------------------------------------------------------------
extern "C" void kernel_launch(void* const* d_in, const int* in_sizes, int n_in,
                              void* d_out, int out_size)
{
    (void)in_sizes; (void)n_in; (void)out_size;

    const float* x        = (const float*)d_in[0];
    const float* W_in     = (const float*)d_in[1];
    const float* b_in     = (const float*)d_in[2];
    const float* g_in     = (const float*)d_in[3];
    const float* beta_in  = (const float*)d_in[4];
    const float* W_q      = (const float*)d_in[5];
    const float* W_k      = (const float*)d_in[6];
    const float* W_v      = (const float*)d_in[7];
    const float* g_out    = (const float*)d_in[8];
    const float* beta_out = (const float*)d_in[9];
    const float* W_out    = (const float*)d_in[10];
    const float* b_out    = (const float*)d_in[11];
    float* out = (float*)d_out;

    float* t0;
    __half *qh, *kh, *vh, *af, *wt;
    cudaGetSymbolAddress((void**)&t0, g_t0);
    cudaGetSymbolAddress((void**)&qh, g_qh);
    cudaGetSymbolAddress((void**)&kh, g_kh);
    cudaGetSymbolAddress((void**)&vh, g_vh);
    cudaGetSymbolAddress((void**)&af, g_af);
    cudaGetSymbolAddress((void**)&wt, g_wt);

    cudaFuncSetAttribute(gemm_f32, cudaFuncAttributeMaxDynamicSharedMemorySize, GSMEM);
    cudaFuncSetAttribute(gemm_qkv, cudaFuncAttributeMaxDynamicSharedMemorySize, GSMEM);

    const size_t WSLOT = 1024ull * 1024ull;
    const dim3 wsGrid(32, 32), wsBlk(32, 8);
    const int n4 = PNL * PD / 4;
    const int cvtBlocks = (n4 + 255) / 256;
    const dim3 gemmBlk(256);

    // weight transforms
    wtrans_kernel<<<wsGrid, wsBlk>>>(W_in,  wt + 0 * WSLOT);
    wtrans_kernel<<<wsGrid, wsBlk>>>(W_q,   wt + 1 * WSLOT);
    wtrans_kernel<<<wsGrid, wsBlk>>>(W_k,   wt + 2 * WSLOT);
    wtrans_kernel<<<wsGrid, wsBlk>>>(W_v,   wt + 3 * WSLOT);
    wtrans_kernel<<<wsGrid, wsBlk>>>(W_out, wt + 4 * WSLOT);

    // 1. t0 = x @ W_in + b_in
    tohalf_kernel<<<cvtBlocks, 256>>>(x, af, n4);
    gemm_f32<<<dim3(8, 197), gemmBlk, GSMEM>>>(PNL, af, wt + 0 * WSLOT, b_in, t0);
    // 2. af = fp16(LN(t0))
    ln_half_kernel<<<PNL, 256>>>(t0, g_in, beta_in, af);
    // 3. fused q/k/v projection (N=3072, weight slots 1-3 contiguous), fp16 out
    gemm_qkv<<<dim3(24, 197), gemmBlk, GSMEM>>>(PNL, af, wt + 1 * WSLOT, qh, kh, vh);
    // 4. temporal attention -> t0
    attn_kernel<<<dim3(PS, PN * PH), 128>>>(qh, kh, vh, t0);
    // 5. af = fp16(LN(t0))
    ln_half_kernel<<<PNL, 256>>>(t0, g_out, beta_out, af);
    // 6. out = af @ W_out + b_out
    gemm_f32<<<dim3(8, 197), gemmBlk, GSMEM>>>(PNL, af, wt + 4 * WSLOT, b_out, out);
}

// round 14
// speedup vs baseline: 2.2637x; 1.0593x over previous
#include <cuda_runtime.h>
#include <cuda_fp16.h>
#include <cstdint>
#include <math.h>

// Problem constants
#define PN   8
#define PF   16
#define PS   196
#define PD   1024
#define PH   8
#define PHD  128
#define PL   (1 + PF * PS)        // 3137
#define PNL  (PN * PL)            // 25096

// ---------------------------------------------------------------------------
// Scratch (device globals)
// ---------------------------------------------------------------------------
__device__ __half g_t0h[(size_t)PNL * PD];           // intermediate (fp16)
__device__ __half g_qh[(size_t)PNL * PD];
__device__ __half g_kh[(size_t)PNL * PD];
__device__ __half g_vh[(size_t)PNL * PD];
__device__ __half g_af[(size_t)PNL * PD];            // activations, fp16
__device__ __half g_wt[5ull * 1024 * 1024];          // transposed weights, fp16

// ---------------------------------------------------------------------------
// Helpers
// ---------------------------------------------------------------------------
__device__ __forceinline__ uint32_t smem_u32(const void* p) {
    uint32_t a;
    asm("{ .reg .u64 t; cvta.to.shared.u64 t, %1; cvt.u32.u64 %0, t; }" : "=r"(a) : "l"(p));
    return a;
}

#define LDM_X4(d0, d1, d2, d3, addr)                                             \
    asm volatile("ldmatrix.sync.aligned.m8n8.x4.shared.b16 {%0,%1,%2,%3}, [%4];" \
                 : "=r"(d0), "=r"(d1), "=r"(d2), "=r"(d3) : "r"(addr))
#define MMA_F16(d, a0, a1, a2, a3, b0, b1)                                       \
    asm volatile("mma.sync.aligned.m16n8k16.row.col.f32.f16.f16.f32 "            \
                 "{%0,%1,%2,%3}, {%4,%5,%6,%7}, {%8,%9}, {%0,%1,%2,%3};"         \
                 : "+f"((d)[0]), "+f"((d)[1]), "+f"((d)[2]), "+f"((d)[3])        \
                 : "r"(a0), "r"(a1), "r"(a2), "r"(a3), "r"(b0), "r"(b1))
#define CP_ASYNC16(dst, src, sz)                                                 \
    asm volatile("cp.async.cg.shared.global [%0], [%1], 16, %2;"                 \
                 :: "r"(dst), "l"(src), "r"(sz) : "memory")
#define CP_COMMIT()       asm volatile("cp.async.commit_group;" ::: "memory")
#define CP_WAIT_GROUP1()  asm volatile("cp.async.wait_group 1;" ::: "memory")

// ---------------------------------------------------------------------------
// Convert fp32 -> fp16 (elementwise)
// ---------------------------------------------------------------------------
__global__ __launch_bounds__(256)
void tohalf_kernel(const float* __restrict__ in, __half* __restrict__ o16, int n4)
{
    int i = blockIdx.x * blockDim.x + threadIdx.x;
    if (i >= n4) return;
    float4 x = ((const float4*)in)[i];
    ((__half2*)o16)[2 * i]     = __floats2half2_rn(x.x, x.y);
    ((__half2*)o16)[2 * i + 1] = __floats2half2_rn(x.z, x.w);
}

// ---------------------------------------------------------------------------
// Transpose all 5 weights: W[k][n] fp32 -> Wt[n][k] fp16 (blockIdx.z = slot)
// ---------------------------------------------------------------------------
__global__ __launch_bounds__(256)
void wtrans5_kernel(const float* __restrict__ W0, const float* __restrict__ W1,
                    const float* __restrict__ W2, const float* __restrict__ W3,
                    const float* __restrict__ W4, __half* __restrict__ oBase)
{
    __shared__ float t[32][33];
    const int slot = blockIdx.z;
    const float* W = (slot == 0) ? W0 : (slot == 1) ? W1 : (slot == 2) ? W2
                   : (slot == 3) ? W3 : W4;
    __half* o16 = oBase + (size_t)slot * 1024 * 1024;

    const int bx = blockIdx.x, by = blockIdx.y;
    const int tx = threadIdx.x, ty = threadIdx.y;   // 32 x 8
    #pragma unroll
    for (int i = 0; i < 32; i += 8)
        t[ty + i][tx] = W[(size_t)(by * 32 + ty + i) * 1024 + bx * 32 + tx];
    __syncthreads();
    #pragma unroll
    for (int i = 0; i < 32; i += 8) {
        size_t o = (size_t)(bx * 32 + ty + i) * 1024 + by * 32 + tx;
        o16[o] = __float2half_rn(t[tx][ty + i]);
    }
}

// ---------------------------------------------------------------------------
// Shared fp16 warp-MMA mainloop: 128x128 tile at (m0, n0), BK=32, 3-stage
// cp.async pipeline (wait_group 1), 1 sync/chunk. Accumulates acc[4][4][4].
// ---------------------------------------------------------------------------
#define ST 40                        // smem row stride in fp16 (80B)
#define ARR_B   (128 * ST * 2)       // bytes per array (10240)
#define STAGE_B (2 * ARR_B)          // bytes per stage (20480): A, B
#define GSMEM   (3 * STAGE_B)        // total dynamic smem (61440)

extern __shared__ __half dynsmem[];

__device__ __forceinline__ void gemm_mainloop(
    int M, const __half* __restrict__ aF, const __half* __restrict__ bT,
    int m0, int n0, int tid, int wid, int lane, float acc[4][4][4])
{
    const int wm = (wid >> 2) * 64;
    const int wn = (wid & 3) * 32;
    const uint32_t sbase = smem_u32(dynsmem);

    #define LOAD_STAGE(c, sb) do {                                               \
        const int kk0 = (c) * 32;                                                \
        _Pragma("unroll")                                                        \
        for (int i = 0; i < 4; i++) {                                            \
            int idx = tid + i * 256;                                             \
            int grp = idx >> 9, within = idx & 511;                              \
            int row = within >> 2, c16 = within & 3;                             \
            int kc  = kk0 + c16 * 8;                                             \
            uint32_t dst = (sb) + grp * ARR_B + (row * ST + c16 * 8) * 2;        \
            const __half* src;                                                   \
            uint32_t sz = 16;                                                    \
            if (grp == 0) {                                                      \
                int m = m0 + row;                                                \
                if (m >= M) { m = m0; sz = 0; }                                  \
                src = aF + (size_t)m * 1024 + kc;                                \
            } else {                                                             \
                src = bT + (size_t)(n0 + row) * 1024 + kc;                       \
            }                                                                    \
            CP_ASYNC16(dst, src, sz);                                            \
        }                                                                        \
        CP_COMMIT();                                                             \
    } while (0)

    LOAD_STAGE(0, sbase);
    LOAD_STAGE(1, sbase + STAGE_B);

    const int aRow = wm + (lane & 15);
    const int aKof = (lane >> 4) * 8;
    const int bRow = wn + (lane & 7) + ((lane >> 4) << 3);
    const int bKof = ((lane >> 3) & 1) * 8;

    int s3 = 0;                       // c % 3
    int s3n = 2;                      // (c+2) % 3
    for (int c = 0; c < 32; c++) {
        const uint32_t cur = sbase + s3 * STAGE_B;
        CP_WAIT_GROUP1();             // stage c arrived (c+1 may be in flight)
        __syncthreads();              // all warps done reading buffer (c-1)%3
        if (c < 30) LOAD_STAGE(c + 2, sbase + s3n * STAGE_B);
        else        CP_COMMIT();      // empty group keeps wait_group aligned

        const uint32_t Aa = cur, Bb = cur + ARR_B;

        #pragma unroll
        for (int ks = 0; ks < 2; ks++) {
            const int kb = ks * 16;
            uint32_t bf[2][4];
            #pragma unroll
            for (int p = 0; p < 2; p++) {
                uint32_t off = ((bRow + p * 16) * ST + kb + bKof) * 2;
                LDM_X4(bf[p][0], bf[p][1], bf[p][2], bf[p][3], Bb + off);
            }
            #pragma unroll
            for (int mt = 0; mt < 4; mt++) {
                uint32_t a0, a1, a2, a3;
                uint32_t off = ((aRow + mt * 16) * ST + kb + aKof) * 2;
                LDM_X4(a0, a1, a2, a3, Aa + off);
                #pragma unroll
                for (int nt = 0; nt < 4; nt++) {
                    const int p = nt >> 1, o = (nt & 1) * 2;
                    MMA_F16(acc[mt][nt], a0, a1, a2, a3, bf[p][o], bf[p][o + 1]);
                }
            }
        }
        s3 = (s3 == 2) ? 0 : s3 + 1;
        s3n = (s3n == 2) ? 0 : s3n + 1;
    }
    #undef LOAD_STAGE
}

// ---------------------------------------------------------------------------
// fp32-output GEMM (+bias): used for W_out (final output buffer)
// ---------------------------------------------------------------------------
__global__ __launch_bounds__(256, 2)
void gemm_f32(int M, const __half* __restrict__ aF, const __half* __restrict__ bT,
              const float* __restrict__ bias, float* __restrict__ C)
{
    const int tid = threadIdx.x, wid = tid >> 5, lane = tid & 31;
    const int m0 = blockIdx.y * 128, n0 = blockIdx.x * 128;

    float acc[4][4][4];
    #pragma unroll
    for (int mt = 0; mt < 4; mt++)
        #pragma unroll
        for (int nt = 0; nt < 4; nt++)
            #pragma unroll
            for (int e = 0; e < 4; e++) acc[mt][nt][e] = 0.0f;

    gemm_mainloop(M, aF, bT, m0, n0, tid, wid, lane, acc);

    const int wm = (wid >> 2) * 64, wn = (wid & 3) * 32;
    const int r = lane >> 2, cpair = (lane & 3) * 2;
    #pragma unroll
    for (int nt = 0; nt < 4; nt++) {
        const int n = n0 + wn + nt * 8 + cpair;
        const float b0 = bias[n], b1 = bias[n + 1];
        #pragma unroll
        for (int mt = 0; mt < 4; mt++) {
            const int m = m0 + wm + mt * 16 + r;
            if (m < M)
                *(float2*)(C + (size_t)m * 1024 + n) =
                    make_float2(acc[mt][nt][0] + b0, acc[mt][nt][1] + b1);
            if (m + 8 < M)
                *(float2*)(C + (size_t)(m + 8) * 1024 + n) =
                    make_float2(acc[mt][nt][2] + b0, acc[mt][nt][3] + b1);
        }
    }
}

// ---------------------------------------------------------------------------
// fp16-output GEMM (+bias): used for W_in (feeds LN1)
// ---------------------------------------------------------------------------
__global__ __launch_bounds__(256, 2)
void gemm_f16(int M, const __half* __restrict__ aF, const __half* __restrict__ bT,
              const float* __restrict__ bias, __half* __restrict__ C)
{
    const int tid = threadIdx.x, wid = tid >> 5, lane = tid & 31;
    const int m0 = blockIdx.y * 128, n0 = blockIdx.x * 128;

    float acc[4][4][4];
    #pragma unroll
    for (int mt = 0; mt < 4; mt++)
        #pragma unroll
        for (int nt = 0; nt < 4; nt++)
            #pragma unroll
            for (int e = 0; e < 4; e++) acc[mt][nt][e] = 0.0f;

    gemm_mainloop(M, aF, bT, m0, n0, tid, wid, lane, acc);

    const int wm = (wid >> 2) * 64, wn = (wid & 3) * 32;
    const int r = lane >> 2, cpair = (lane & 3) * 2;
    #pragma unroll
    for (int nt = 0; nt < 4; nt++) {
        const int n = n0 + wn + nt * 8 + cpair;
        const float b0 = bias[n], b1 = bias[n + 1];
        #pragma unroll
        for (int mt = 0; mt < 4; mt++) {
            const int m = m0 + wm + mt * 16 + r;
            if (m < M)
                *(__half2*)(C + (size_t)m * 1024 + n) =
                    __floats2half2_rn(acc[mt][nt][0] + b0, acc[mt][nt][1] + b1);
            if (m + 8 < M)
                *(__half2*)(C + (size_t)(m + 8) * 1024 + n) =
                    __floats2half2_rn(acc[mt][nt][2] + b0, acc[mt][nt][3] + b1);
        }
    }
}

// ---------------------------------------------------------------------------
// Fused QKV GEMM: N=3072 (weight slots 1-3 contiguous), fp16 outputs into
// q/k/v arrays selected by n0>>10. No bias.
// ---------------------------------------------------------------------------
__global__ __launch_bounds__(256, 2)
void gemm_qkv(int M, const __half* __restrict__ aF, const __half* __restrict__ bT,
              __half* __restrict__ q, __half* __restrict__ k, __half* __restrict__ v)
{
    const int tid = threadIdx.x, wid = tid >> 5, lane = tid & 31;
    const int m0 = blockIdx.y * 128, n0 = blockIdx.x * 128;   // n0 in [0,3072)

    float acc[4][4][4];
    #pragma unroll
    for (int mt = 0; mt < 4; mt++)
        #pragma unroll
        for (int nt = 0; nt < 4; nt++)
            #pragma unroll
            for (int e = 0; e < 4; e++) acc[mt][nt][e] = 0.0f;

    gemm_mainloop(M, aF, bT, m0, n0, tid, wid, lane, acc);

    __half* C = (n0 < 1024) ? q : (n0 < 2048 ? k : v);
    const int nb = n0 & 1023;

    const int wm = (wid >> 2) * 64, wn = (wid & 3) * 32;
    const int r = lane >> 2, cpair = (lane & 3) * 2;
    #pragma unroll
    for (int nt = 0; nt < 4; nt++) {
        const int n = nb + wn + nt * 8 + cpair;
        #pragma unroll
        for (int mt = 0; mt < 4; mt++) {
            const int m = m0 + wm + mt * 16 + r;
            if (m < M)
                *(__half2*)(C + (size_t)m * 1024 + n) =
                    __floats2half2_rn(acc[mt][nt][0], acc[mt][nt][1]);
            if (m + 8 < M)
                *(__half2*)(C + (size_t)(m + 8) * 1024 + n) =
                    __floats2half2_rn(acc[mt][nt][2], acc[mt][nt][3]);
        }
    }
}

// ---------------------------------------------------------------------------
// LayerNorm over rows of 1024, fp16 in -> fp16 out (fp32 math)
// ---------------------------------------------------------------------------
__global__ __launch_bounds__(256)
void ln_half_kernel(const __half* __restrict__ in, const float* __restrict__ gamma,
                    const float* __restrict__ beta, __half* __restrict__ o16)
{
    const int row = blockIdx.x;
    const int t   = threadIdx.x;
    const __half2* x2 = (const __half2*)(in + (size_t)row * PD);
    float2 fa = __half22float2(x2[2 * t]);
    float2 fb = __half22float2(x2[2 * t + 1]);

    float s  = fa.x + fa.y + fb.x + fb.y;
    float s2 = fa.x * fa.x + fa.y * fa.y + fb.x * fb.x + fb.y * fb.y;

    __shared__ float red[2][8];
    #pragma unroll
    for (int o = 16; o > 0; o >>= 1) {
        s  += __shfl_down_sync(0xFFFFFFFFu, s,  o);
        s2 += __shfl_down_sync(0xFFFFFFFFu, s2, o);
    }
    const int wid = t >> 5, lid = t & 31;
    if (lid == 0) { red[0][wid] = s; red[1][wid] = s2; }
    __syncthreads();
    if (wid == 0) {
        float a = (lid < 8) ? red[0][lid] : 0.f;
        float b = (lid < 8) ? red[1][lid] : 0.f;
        #pragma unroll
        for (int o = 4; o > 0; o >>= 1) {
            a += __shfl_down_sync(0xFFFFFFFFu, a, o);
            b += __shfl_down_sync(0xFFFFFFFFu, b, o);
        }
        if (lid == 0) { red[0][0] = a; red[1][0] = b; }
    }
    __syncthreads();

    const float mean = red[0][0] * (1.0f / PD);
    const float var  = red[1][0] * (1.0f / PD) - mean * mean;
    const float rstd = rsqrtf(var + 1e-5f);

    float4 gv = ((const float4*)gamma)[t];
    float4 bv = ((const float4*)beta)[t];
    float o0 = (fa.x - mean) * rstd * gv.x + bv.x;
    float o1 = (fa.y - mean) * rstd * gv.y + bv.y;
    float o2 = (fb.x - mean) * rstd * gv.z + bv.z;
    float o3 = (fb.y - mean) * rstd * gv.w + bv.w;

    const size_t o = (size_t)row * PD / 2 + 2 * t;
    ((__half2*)o16)[o]     = __floats2half2_rn(o0, o1);
    ((__half2*)o16)[o + 1] = __floats2half2_rn(o2, o3);
}

// ---------------------------------------------------------------------------
// Temporal attention (att_type == 1), fp16 q/k/v in, fp16 out, fp32 compute.
// q/k in packed fp16 smem (halved LDS in score loop); v fp32 smem.
// Reference tile quirk: feature K/V for attention batch b = nh*S + s comes
// from head-batch (b % 64).
// ---------------------------------------------------------------------------
__global__ __launch_bounds__(128)
void attn_kernel(const __half* __restrict__ Q, const __half* __restrict__ Kt,
                 const __half* __restrict__ Vt, __half* __restrict__ O)
{
    constexpr int HP = 130;            // half pitch (65 half2) per row
    constexpr int PITCH = 129;         // fp32 pitch for v
    __shared__ __align__(4) __half qs_h[16 * HP];
    __shared__ __align__(4) __half ks_h[17 * HP];
    __shared__ float vs[17 * PITCH];
    __shared__ float ps[16 * 18];

    const int s  = blockIdx.x;         // 0..195
    const int nh = blockIdx.y;         // 0..63
    const int n  = nh >> 3;
    const int h  = nh & 7;
    const int t  = threadIdx.x;        // 0..127

    const int fb = (nh * PS + s) & 63;
    const int fn = fb >> 3;
    const int fh = fb & 7;
    const size_t featKV = ((size_t)fn * PL) * PD + (size_t)fh * PHD;
    ks_h[t] = Kt[featKV + t];
    vs[t]   = __half2float(Vt[featKV + t]);

    for (int f = 0; f < PF; f++) {
        const size_t r = ((size_t)n * PL + 1 + (size_t)f * PS + s) * PD + (size_t)h * PHD;
        qs_h[f * HP + t]       = Q [r + t];
        ks_h[(f + 1) * HP + t] = Kt[r + t];
        vs[(f + 1) * PITCH + t] = __half2float(Vt[r + t]);
    }
    __syncthreads();

    const float scale = 0.088388347648318447f;   // 1/sqrt(128)
    for (int p = t; p < 16 * 17; p += 128) {
        const int i = p / 17, j = p % 17;
        const __half2* q2 = (const __half2*)qs_h + i * (HP / 2);
        const __half2* k2 = (const __half2*)ks_h + j * (HP / 2);
        float acc = 0.f;
        #pragma unroll 8
        for (int d2 = 0; d2 < PHD / 2; d2++) {
            float2 a = __half22float2(q2[d2]);
            float2 b = __half22float2(k2[d2]);
            acc = fmaf(a.x, b.x, acc);
            acc = fmaf(a.y, b.y, acc);
        }
        ps[i * 18 + j] = acc * scale;
    }
    __syncthreads();

    if (t < 16) {
        float mx = -1e30f;
        #pragma unroll
        for (int j = 0; j < 17; j++) mx = fmaxf(mx, ps[t * 18 + j]);
        float sum = 0.f;
        #pragma unroll
        for (int j = 0; j < 17; j++) {
            const float e = __expf(ps[t * 18 + j] - mx);
            ps[t * 18 + j] = e;
            sum += e;
        }
        const float inv = 1.0f / sum;
        #pragma unroll
        for (int j = 0; j < 17; j++) ps[t * 18 + j] *= inv;
    }
    __syncthreads();

    for (int i = 0; i < PF; i++) {
        float acc = 0.f;
        #pragma unroll
        for (int j = 0; j < 17; j++)
            acc = fmaf(ps[i * 18 + j], vs[j * PITCH + t], acc);
        O[((size_t)n * PL + 1 + (size_t)i * PS + s) * PD + (size_t)h * PHD + t] =
            __float2half_rn(acc);
    }

    if (s == 0) {
        const size_t featRow = ((size_t)n * PL) * PD + (size_t)h * PHD;
        O[featRow + t] = Q[featRow + t];
    }
}

// ---------------------------------------------------------------------------
// Launch
// ---------------------------------------------------------------------------
extern "C" void kernel_launch(void* const* d_in, const int* in_sizes, int n_in,
                              void* d_out, int out_size)
{
    (void)in_sizes; (void)n_in; (void)out_size;

    const float* x        = (const float*)d_in[0];
    const float* W_in     = (const float*)d_in[1];
    const float* b_in     = (const float*)d_in[2];
    const float* g_in     = (const float*)d_in[3];
    const float* beta_in  = (const float*)d_in[4];
    const float* W_q      = (const float*)d_in[5];
    const float* W_k      = (const float*)d_in[6];
    const float* W_v      = (const float*)d_in[7];
    const float* g_out    = (const float*)d_in[8];
    const float* beta_out = (const float*)d_in[9];
    const float* W_out    = (const float*)d_in[10];
    const float* b_out    = (const float*)d_in[11];
    float* out = (float*)d_out;

    __half *t0h, *qh, *kh, *vh, *af, *wt;
    cudaGetSymbolAddress((void**)&t0h, g_t0h);
    cudaGetSymbolAddress((void**)&qh,  g_qh);
    cudaGetSymbolAddress((void**)&kh,  g_kh);
    cudaGetSymbolAddress((void**)&vh,  g_vh);
    cudaGetSymbolAddress((void**)&af,  g_af);
    cudaGetSymbolAddress((void**)&wt,  g_wt);

    cudaFuncSetAttribute(gemm_f32, cudaFuncAttributeMaxDynamicSharedMemorySize, GSMEM);
    cudaFuncSetAttribute(gemm_f16, cudaFuncAttributeMaxDynamicSharedMemorySize, GSMEM);
    cudaFuncSetAttribute(gemm_qkv, cudaFuncAttributeMaxDynamicSharedMemorySize, GSMEM);

    const size_t WSLOT = 1024ull * 1024ull;
    const int n4 = PNL * PD / 4;
    const int cvtBlocks = (n4 + 255) / 256;
    const dim3 gemmBlk(256);

    // all weight transforms in one launch
    wtrans5_kernel<<<dim3(32, 32, 5), dim3(32, 8)>>>(W_in, W_q, W_k, W_v, W_out, wt);

    // 1. t0h = fp16(x @ W_in + b_in)
    tohalf_kernel<<<cvtBlocks, 256>>>(x, af, n4);
    gemm_f16<<<dim3(8, 197), gemmBlk, GSMEM>>>(PNL, af, wt + 0 * WSLOT, b_in, t0h);
    // 2. af = fp16(LN(t0h))
    ln_half_kernel<<<PNL, 256>>>(t0h, g_in, beta_in, af);
    // 3. fused q/k/v projection (N=3072, weight slots 1-3 contiguous), fp16 out
    gemm_qkv<<<dim3(24, 197), gemmBlk, GSMEM>>>(PNL, af, wt + 1 * WSLOT, qh, kh, vh);
    // 4. temporal attention -> t0h (fp16)
    attn_kernel<<<dim3(PS, PN * PH), 128>>>(qh, kh, vh, t0h);
    // 5. af = fp16(LN(t0h))
    ln_half_kernel<<<PNL, 256>>>(t0h, g_out, beta_out, af);
    // 6. out = af @ W_out + b_out (fp32)
    gemm_f32<<<dim3(8, 197), gemmBlk, GSMEM>>>(PNL, af, wt + 4 * WSLOT, b_out, out);
}

// round 15
// speedup vs baseline: 2.3044x; 1.0180x over previous
#include <cuda_runtime.h>
#include <cuda_fp16.h>
#include <cstdint>
#include <math.h>

// Problem constants
#define PN   8
#define PF   16
#define PS   196
#define PD   1024
#define PH   8
#define PHD  128
#define PL   (1 + PF * PS)        // 3137
#define PNL  (PN * PL)            // 25096

// ---------------------------------------------------------------------------
// Scratch (device globals)
// ---------------------------------------------------------------------------
__device__ __half g_t0h[(size_t)PNL * PD];           // intermediate (fp16)
__device__ __half g_qh[(size_t)PNL * PD];
__device__ __half g_kh[(size_t)PNL * PD];
__device__ __half g_vh[(size_t)PNL * PD];
__device__ __half g_af[(size_t)PNL * PD];            // activations, fp16
__device__ __half g_wt[5ull * 1024 * 1024];          // transposed weights, fp16

// ---------------------------------------------------------------------------
// Helpers
// ---------------------------------------------------------------------------
__device__ __forceinline__ uint32_t smem_u32(const void* p) {
    uint32_t a;
    asm("{ .reg .u64 t; cvta.to.shared.u64 t, %1; cvt.u32.u64 %0, t; }" : "=r"(a) : "l"(p));
    return a;
}

#define LDM_X4(d0, d1, d2, d3, addr)                                             \
    asm volatile("ldmatrix.sync.aligned.m8n8.x4.shared.b16 {%0,%1,%2,%3}, [%4];" \
                 : "=r"(d0), "=r"(d1), "=r"(d2), "=r"(d3) : "r"(addr))
#define MMA_F16(d, a0, a1, a2, a3, b0, b1)                                       \
    asm volatile("mma.sync.aligned.m16n8k16.row.col.f32.f16.f16.f32 "            \
                 "{%0,%1,%2,%3}, {%4,%5,%6,%7}, {%8,%9}, {%0,%1,%2,%3};"         \
                 : "+f"((d)[0]), "+f"((d)[1]), "+f"((d)[2]), "+f"((d)[3])        \
                 : "r"(a0), "r"(a1), "r"(a2), "r"(a3), "r"(b0), "r"(b1))
#define CP_ASYNC16(dst, src, sz)                                                 \
    asm volatile("cp.async.cg.shared.global [%0], [%1], 16, %2;"                 \
                 :: "r"(dst), "l"(src), "r"(sz) : "memory")
#define CP_COMMIT()       asm volatile("cp.async.commit_group;" ::: "memory")
#define CP_WAIT_GROUP1()  asm volatile("cp.async.wait_group 1;" ::: "memory")

// ---------------------------------------------------------------------------
// Convert fp32 -> fp16 (elementwise)
// ---------------------------------------------------------------------------
__global__ __launch_bounds__(256)
void tohalf_kernel(const float* __restrict__ in, __half* __restrict__ o16, int n4)
{
    int i = blockIdx.x * blockDim.x + threadIdx.x;
    if (i >= n4) return;
    float4 x = ((const float4*)in)[i];
    ((__half2*)o16)[2 * i]     = __floats2half2_rn(x.x, x.y);
    ((__half2*)o16)[2 * i + 1] = __floats2half2_rn(x.z, x.w);
}

// ---------------------------------------------------------------------------
// Transpose all 5 weights: W[k][n] fp32 -> Wt[n][k] fp16 (blockIdx.z = slot)
// ---------------------------------------------------------------------------
__global__ __launch_bounds__(256)
void wtrans5_kernel(const float* __restrict__ W0, const float* __restrict__ W1,
                    const float* __restrict__ W2, const float* __restrict__ W3,
                    const float* __restrict__ W4, __half* __restrict__ oBase)
{
    __shared__ float t[32][33];
    const int slot = blockIdx.z;
    const float* W = (slot == 0) ? W0 : (slot == 1) ? W1 : (slot == 2) ? W2
                   : (slot == 3) ? W3 : W4;
    __half* o16 = oBase + (size_t)slot * 1024 * 1024;

    const int bx = blockIdx.x, by = blockIdx.y;
    const int tx = threadIdx.x, ty = threadIdx.y;   // 32 x 8
    #pragma unroll
    for (int i = 0; i < 32; i += 8)
        t[ty + i][tx] = W[(size_t)(by * 32 + ty + i) * 1024 + bx * 32 + tx];
    __syncthreads();
    #pragma unroll
    for (int i = 0; i < 32; i += 8) {
        size_t o = (size_t)(bx * 32 + ty + i) * 1024 + by * 32 + tx;
        o16[o] = __float2half_rn(t[tx][ty + i]);
    }
}

// ---------------------------------------------------------------------------
// Shared fp16 warp-MMA mainloop: 128x128 tile at (m0, n0), BK=32, 3-stage
// cp.async pipeline (wait_group 1), 1 sync/chunk. Accumulates acc[4][4][4].
// ---------------------------------------------------------------------------
#define ST 40                        // smem row stride in fp16 (80B)
#define ARR_B   (128 * ST * 2)       // bytes per array (10240)
#define STAGE_B (2 * ARR_B)          // bytes per stage (20480): A, B
#define GSMEM   (3 * STAGE_B)        // total dynamic smem (61440)

extern __shared__ __half dynsmem[];

__device__ __forceinline__ void gemm_mainloop(
    int M, const __half* __restrict__ aF, const __half* __restrict__ bT,
    int m0, int n0, int tid, int wid, int lane, float acc[4][4][4])
{
    const int wm = (wid >> 2) * 64;
    const int wn = (wid & 3) * 32;
    const uint32_t sbase = smem_u32(dynsmem);

    #define LOAD_STAGE(c, sb) do {                                               \
        const int kk0 = (c) * 32;                                                \
        _Pragma("unroll")                                                        \
        for (int i = 0; i < 4; i++) {                                            \
            int idx = tid + i * 256;                                             \
            int grp = idx >> 9, within = idx & 511;                              \
            int row = within >> 2, c16 = within & 3;                             \
            int kc  = kk0 + c16 * 8;                                             \
            uint32_t dst = (sb) + grp * ARR_B + (row * ST + c16 * 8) * 2;        \
            const __half* src;                                                   \
            uint32_t sz = 16;                                                    \
            if (grp == 0) {                                                      \
                int m = m0 + row;                                                \
                if (m >= M) { m = m0; sz = 0; }                                  \
                src = aF + (size_t)m * 1024 + kc;                                \
            } else {                                                             \
                src = bT + (size_t)(n0 + row) * 1024 + kc;                       \
            }                                                                    \
            CP_ASYNC16(dst, src, sz);                                            \
        }                                                                        \
        CP_COMMIT();                                                             \
    } while (0)

    LOAD_STAGE(0, sbase);
    LOAD_STAGE(1, sbase + STAGE_B);

    const int aRow = wm + (lane & 15);
    const int aKof = (lane >> 4) * 8;
    const int bRow = wn + (lane & 7) + ((lane >> 4) << 3);
    const int bKof = ((lane >> 3) & 1) * 8;

    int s3 = 0;                       // c % 3
    int s3n = 2;                      // (c+2) % 3
    for (int c = 0; c < 32; c++) {
        const uint32_t cur = sbase + s3 * STAGE_B;
        CP_WAIT_GROUP1();             // stage c arrived (c+1 may be in flight)
        __syncthreads();              // all warps done reading buffer (c-1)%3
        if (c < 30) LOAD_STAGE(c + 2, sbase + s3n * STAGE_B);
        else        CP_COMMIT();      // empty group keeps wait_group aligned

        const uint32_t Aa = cur, Bb = cur + ARR_B;

        #pragma unroll
        for (int ks = 0; ks < 2; ks++) {
            const int kb = ks * 16;
            uint32_t bf[2][4];
            #pragma unroll
            for (int p = 0; p < 2; p++) {
                uint32_t off = ((bRow + p * 16) * ST + kb + bKof) * 2;
                LDM_X4(bf[p][0], bf[p][1], bf[p][2], bf[p][3], Bb + off);
            }
            #pragma unroll
            for (int mt = 0; mt < 4; mt++) {
                uint32_t a0, a1, a2, a3;
                uint32_t off = ((aRow + mt * 16) * ST + kb + aKof) * 2;
                LDM_X4(a0, a1, a2, a3, Aa + off);
                #pragma unroll
                for (int nt = 0; nt < 4; nt++) {
                    const int p = nt >> 1, o = (nt & 1) * 2;
                    MMA_F16(acc[mt][nt], a0, a1, a2, a3, bf[p][o], bf[p][o + 1]);
                }
            }
        }
        s3 = (s3 == 2) ? 0 : s3 + 1;
        s3n = (s3n == 2) ? 0 : s3n + 1;
    }
    #undef LOAD_STAGE
}

// ---------------------------------------------------------------------------
// fp32-output GEMM (+bias): used for W_out (final output buffer)
// ---------------------------------------------------------------------------
__global__ __launch_bounds__(256, 2)
void gemm_f32(int M, const __half* __restrict__ aF, const __half* __restrict__ bT,
              const float* __restrict__ bias, float* __restrict__ C)
{
    const int tid = threadIdx.x, wid = tid >> 5, lane = tid & 31;
    const int m0 = blockIdx.y * 128, n0 = blockIdx.x * 128;

    float acc[4][4][4];
    #pragma unroll
    for (int mt = 0; mt < 4; mt++)
        #pragma unroll
        for (int nt = 0; nt < 4; nt++)
            #pragma unroll
            for (int e = 0; e < 4; e++) acc[mt][nt][e] = 0.0f;

    gemm_mainloop(M, aF, bT, m0, n0, tid, wid, lane, acc);

    const int wm = (wid >> 2) * 64, wn = (wid & 3) * 32;
    const int r = lane >> 2, cpair = (lane & 3) * 2;
    #pragma unroll
    for (int nt = 0; nt < 4; nt++) {
        const int n = n0 + wn + nt * 8 + cpair;
        const float b0 = bias[n], b1 = bias[n + 1];
        #pragma unroll
        for (int mt = 0; mt < 4; mt++) {
            const int m = m0 + wm + mt * 16 + r;
            if (m < M)
                *(float2*)(C + (size_t)m * 1024 + n) =
                    make_float2(acc[mt][nt][0] + b0, acc[mt][nt][1] + b1);
            if (m + 8 < M)
                *(float2*)(C + (size_t)(m + 8) * 1024 + n) =
                    make_float2(acc[mt][nt][2] + b0, acc[mt][nt][3] + b1);
        }
    }
}

// ---------------------------------------------------------------------------
// fp16-output GEMM (+bias): used for W_in (feeds LN1)
// ---------------------------------------------------------------------------
__global__ __launch_bounds__(256, 2)
void gemm_f16(int M, const __half* __restrict__ aF, const __half* __restrict__ bT,
              const float* __restrict__ bias, __half* __restrict__ C)
{
    const int tid = threadIdx.x, wid = tid >> 5, lane = tid & 31;
    const int m0 = blockIdx.y * 128, n0 = blockIdx.x * 128;

    float acc[4][4][4];
    #pragma unroll
    for (int mt = 0; mt < 4; mt++)
        #pragma unroll
        for (int nt = 0; nt < 4; nt++)
            #pragma unroll
            for (int e = 0; e < 4; e++) acc[mt][nt][e] = 0.0f;

    gemm_mainloop(M, aF, bT, m0, n0, tid, wid, lane, acc);

    const int wm = (wid >> 2) * 64, wn = (wid & 3) * 32;
    const int r = lane >> 2, cpair = (lane & 3) * 2;
    #pragma unroll
    for (int nt = 0; nt < 4; nt++) {
        const int n = n0 + wn + nt * 8 + cpair;
        const float b0 = bias[n], b1 = bias[n + 1];
        #pragma unroll
        for (int mt = 0; mt < 4; mt++) {
            const int m = m0 + wm + mt * 16 + r;
            if (m < M)
                *(__half2*)(C + (size_t)m * 1024 + n) =
                    __floats2half2_rn(acc[mt][nt][0] + b0, acc[mt][nt][1] + b1);
            if (m + 8 < M)
                *(__half2*)(C + (size_t)(m + 8) * 1024 + n) =
                    __floats2half2_rn(acc[mt][nt][2] + b0, acc[mt][nt][3] + b1);
        }
    }
}

// ---------------------------------------------------------------------------
// Fused QKV GEMM: N=3072 (weight slots 1-3 contiguous), fp16 outputs into
// q/k/v arrays selected by n0>>10. No bias.
// ---------------------------------------------------------------------------
__global__ __launch_bounds__(256, 2)
void gemm_qkv(int M, const __half* __restrict__ aF, const __half* __restrict__ bT,
              __half* __restrict__ q, __half* __restrict__ k, __half* __restrict__ v)
{
    const int tid = threadIdx.x, wid = tid >> 5, lane = tid & 31;
    const int m0 = blockIdx.y * 128, n0 = blockIdx.x * 128;   // n0 in [0,3072)

    float acc[4][4][4];
    #pragma unroll
    for (int mt = 0; mt < 4; mt++)
        #pragma unroll
        for (int nt = 0; nt < 4; nt++)
            #pragma unroll
            for (int e = 0; e < 4; e++) acc[mt][nt][e] = 0.0f;

    gemm_mainloop(M, aF, bT, m0, n0, tid, wid, lane, acc);

    __half* C = (n0 < 1024) ? q : (n0 < 2048 ? k : v);
    const int nb = n0 & 1023;

    const int wm = (wid >> 2) * 64, wn = (wid & 3) * 32;
    const int r = lane >> 2, cpair = (lane & 3) * 2;
    #pragma unroll
    for (int nt = 0; nt < 4; nt++) {
        const int n = nb + wn + nt * 8 + cpair;
        #pragma unroll
        for (int mt = 0; mt < 4; mt++) {
            const int m = m0 + wm + mt * 16 + r;
            if (m < M)
                *(__half2*)(C + (size_t)m * 1024 + n) =
                    __floats2half2_rn(acc[mt][nt][0], acc[mt][nt][1]);
            if (m + 8 < M)
                *(__half2*)(C + (size_t)(m + 8) * 1024 + n) =
                    __floats2half2_rn(acc[mt][nt][2], acc[mt][nt][3]);
        }
    }
}

// ---------------------------------------------------------------------------
// Warp-per-row LayerNorm: fp16 in -> fp16 out (fp32 math), 8 rows per block.
// Each lane holds 32 elements (4 x 16B); shfl_xor butterfly reduction — no
// smem, no __syncthreads.
// ---------------------------------------------------------------------------
__global__ __launch_bounds__(256)
void ln_warp_kernel(const __half* __restrict__ in, const float* __restrict__ gamma,
                    const float* __restrict__ beta, __half* __restrict__ o16)
{
    const int row  = blockIdx.x * 8 + (threadIdx.x >> 5);
    const int lane = threadIdx.x & 31;
    const uint4* rp = (const uint4*)(in + (size_t)row * PD);   // 128 x 16B chunks

    uint4 d[4];
    #pragma unroll
    for (int i = 0; i < 4; i++) d[i] = rp[lane + 32 * i];

    float s = 0.f, s2 = 0.f;
    #pragma unroll
    for (int i = 0; i < 4; i++) {
        const __half2* h2 = (const __half2*)&d[i];
        #pragma unroll
        for (int j = 0; j < 4; j++) {
            float2 f = __half22float2(h2[j]);
            s  += f.x + f.y;
            s2 += f.x * f.x + f.y * f.y;
        }
    }
    #pragma unroll
    for (int o = 16; o > 0; o >>= 1) {
        s  += __shfl_xor_sync(0xFFFFFFFFu, s,  o);
        s2 += __shfl_xor_sync(0xFFFFFFFFu, s2, o);
    }

    const float mean = s * (1.0f / PD);
    const float var  = s2 * (1.0f / PD) - mean * mean;
    const float rstd = rsqrtf(var + 1e-5f);

    uint4* op = (uint4*)(o16 + (size_t)row * PD);
    #pragma unroll
    for (int i = 0; i < 4; i++) {
        const int k0 = (lane + 32 * i) * 8;
        float4 g0 = *(const float4*)(gamma + k0);
        float4 g1 = *(const float4*)(gamma + k0 + 4);
        float4 b0 = *(const float4*)(beta + k0);
        float4 b1 = *(const float4*)(beta + k0 + 4);
        const __half2* h2 = (const __half2*)&d[i];
        float2 f0 = __half22float2(h2[0]);
        float2 f1 = __half22float2(h2[1]);
        float2 f2 = __half22float2(h2[2]);
        float2 f3 = __half22float2(h2[3]);
        uint4 o;
        __half2* oh = (__half2*)&o;
        oh[0] = __floats2half2_rn((f0.x - mean) * rstd * g0.x + b0.x,
                                  (f0.y - mean) * rstd * g0.y + b0.y);
        oh[1] = __floats2half2_rn((f1.x - mean) * rstd * g0.z + b0.z,
                                  (f1.y - mean) * rstd * g0.w + b0.w);
        oh[2] = __floats2half2_rn((f2.x - mean) * rstd * g1.x + b1.x,
                                  (f2.y - mean) * rstd * g1.y + b1.y);
        oh[3] = __floats2half2_rn((f3.x - mean) * rstd * g1.z + b1.z,
                                  (f3.y - mean) * rstd * g1.w + b1.w);
        op[lane + 32 * i] = o;
    }
}

// ---------------------------------------------------------------------------
// Temporal attention (att_type == 1), fp16 q/k/v in, fp16 out, fp32 compute.
// q/k in packed fp16 smem; v fp32 smem. f-loop fully unrolled (MLP ~48).
// Reference tile quirk: feature K/V for attention batch b = nh*S + s comes
// from head-batch (b % 64).
// ---------------------------------------------------------------------------
__global__ __launch_bounds__(128)
void attn_kernel(const __half* __restrict__ Q, const __half* __restrict__ Kt,
                 const __half* __restrict__ Vt, __half* __restrict__ O)
{
    constexpr int HP = 130;            // half pitch per row
    constexpr int PITCH = 129;         // fp32 pitch for v
    __shared__ __align__(4) __half qs_h[16 * HP];
    __shared__ __align__(4) __half ks_h[17 * HP];
    __shared__ float vs[17 * PITCH];
    __shared__ float ps[16 * 18];

    const int s  = blockIdx.x;         // 0..195
    const int nh = blockIdx.y;         // 0..63
    const int n  = nh >> 3;
    const int h  = nh & 7;
    const int t  = threadIdx.x;        // 0..127

    const int fb = (nh * PS + s) & 63;
    const int fn = fb >> 3;
    const int fh = fb & 7;
    const size_t featKV = ((size_t)fn * PL) * PD + (size_t)fh * PHD;
    ks_h[t] = Kt[featKV + t];
    vs[t]   = __half2float(Vt[featKV + t]);

    #pragma unroll
    for (int f = 0; f < PF; f++) {
        const size_t r = ((size_t)n * PL + 1 + (size_t)f * PS + s) * PD + (size_t)h * PHD;
        qs_h[f * HP + t]        = Q [r + t];
        ks_h[(f + 1) * HP + t]  = Kt[r + t];
        vs[(f + 1) * PITCH + t] = __half2float(Vt[r + t]);
    }
    __syncthreads();

    const float scale = 0.088388347648318447f;   // 1/sqrt(128)
    for (int p = t; p < 16 * 17; p += 128) {
        const int i = p / 17, j = p % 17;
        const __half2* q2 = (const __half2*)qs_h + i * (HP / 2);
        const __half2* k2 = (const __half2*)ks_h + j * (HP / 2);
        float acc = 0.f;
        #pragma unroll 8
        for (int d2 = 0; d2 < PHD / 2; d2++) {
            float2 a = __half22float2(q2[d2]);
            float2 b = __half22float2(k2[d2]);
            acc = fmaf(a.x, b.x, acc);
            acc = fmaf(a.y, b.y, acc);
        }
        ps[i * 18 + j] = acc * scale;
    }
    __syncthreads();

    if (t < 16) {
        float mx = -1e30f;
        #pragma unroll
        for (int j = 0; j < 17; j++) mx = fmaxf(mx, ps[t * 18 + j]);
        float sum = 0.f;
        #pragma unroll
        for (int j = 0; j < 17; j++) {
            const float e = __expf(ps[t * 18 + j] - mx);
            ps[t * 18 + j] = e;
            sum += e;
        }
        const float inv = 1.0f / sum;
        #pragma unroll
        for (int j = 0; j < 17; j++) ps[t * 18 + j] *= inv;
    }
    __syncthreads();

    #pragma unroll 4
    for (int i = 0; i < PF; i++) {
        float acc = 0.f;
        #pragma unroll
        for (int j = 0; j < 17; j++)
            acc = fmaf(ps[i * 18 + j], vs[j * PITCH + t], acc);
        O[((size_t)n * PL + 1 + (size_t)i * PS + s) * PD + (size_t)h * PHD + t] =
            __float2half_rn(acc);
    }

    if (s == 0) {
        const size_t featRow = ((size_t)n * PL) * PD + (size_t)h * PHD;
        O[featRow + t] = Q[featRow + t];
    }
}

// ---------------------------------------------------------------------------
// Launch
// ---------------------------------------------------------------------------
extern "C" void kernel_launch(void* const* d_in, const int* in_sizes, int n_in,
                              void* d_out, int out_size)
{
    (void)in_sizes; (void)n_in; (void)out_size;

    const float* x        = (const float*)d_in[0];
    const float* W_in     = (const float*)d_in[1];
    const float* b_in     = (const float*)d_in[2];
    const float* g_in     = (const float*)d_in[3];
    const float* beta_in  = (const float*)d_in[4];
    const float* W_q      = (const float*)d_in[5];
    const float* W_k      = (const float*)d_in[6];
    const float* W_v      = (const float*)d_in[7];
    const float* g_out    = (const float*)d_in[8];
    const float* beta_out = (const float*)d_in[9];
    const float* W_out    = (const float*)d_in[10];
    const float* b_out    = (const float*)d_in[11];
    float* out = (float*)d_out;

    __half *t0h, *qh, *kh, *vh, *af, *wt;
    cudaGetSymbolAddress((void**)&t0h, g_t0h);
    cudaGetSymbolAddress((void**)&qh,  g_qh);
    cudaGetSymbolAddress((void**)&kh,  g_kh);
    cudaGetSymbolAddress((void**)&vh,  g_vh);
    cudaGetSymbolAddress((void**)&af,  g_af);
    cudaGetSymbolAddress((void**)&wt,  g_wt);

    cudaFuncSetAttribute(gemm_f32, cudaFuncAttributeMaxDynamicSharedMemorySize, GSMEM);
    cudaFuncSetAttribute(gemm_f16, cudaFuncAttributeMaxDynamicSharedMemorySize, GSMEM);
    cudaFuncSetAttribute(gemm_qkv, cudaFuncAttributeMaxDynamicSharedMemorySize, GSMEM);

    const size_t WSLOT = 1024ull * 1024ull;
    const int n4 = PNL * PD / 4;
    const int cvtBlocks = (n4 + 255) / 256;
    const dim3 gemmBlk(256);
    const int lnBlocks = PNL / 8;     // 25096 / 8 = 3137

    // all weight transforms in one launch
    wtrans5_kernel<<<dim3(32, 32, 5), dim3(32, 8)>>>(W_in, W_q, W_k, W_v, W_out, wt);

    // 1. t0h = fp16(x @ W_in + b_in)
    tohalf_kernel<<<cvtBlocks, 256>>>(x, af, n4);
    gemm_f16<<<dim3(8, 197), gemmBlk, GSMEM>>>(PNL, af, wt + 0 * WSLOT, b_in, t0h);
    // 2. af = fp16(LN(t0h))
    ln_warp_kernel<<<lnBlocks, 256>>>(t0h, g_in, beta_in, af);
    // 3. fused q/k/v projection (N=3072, weight slots 1-3 contiguous), fp16 out
    gemm_qkv<<<dim3(24, 197), gemmBlk, GSMEM>>>(PNL, af, wt + 1 * WSLOT, qh, kh, vh);
    // 4. temporal attention -> t0h (fp16)
    attn_kernel<<<dim3(PS, PN * PH), 128>>>(qh, kh, vh, t0h);
    // 5. af = fp16(LN(t0h))
    ln_warp_kernel<<<lnBlocks, 256>>>(t0h, g_out, beta_out, af);
    // 6. out = af @ W_out + b_out (fp32)
    gemm_f32<<<dim3(8, 197), gemmBlk, GSMEM>>>(PNL, af, wt + 4 * WSLOT, b_out, out);
}